// round 2
// baseline (speedup 1.0000x reference)
#include <cuda_runtime.h>
#include <math.h>
#include <math_constants.h>

#define BB 2
#define SS 2048
#define DD 1024
#define FF 64
#define TT 28
#define VV 50257
#define MM (BB*SS)   // 4096

// ---------------- scratch (device globals; no allocation allowed) ----------
__device__ float g_x[(size_t)MM*DD];      // running activations  [4096,1024]
__device__ float g_rinv[MM];              // per-row 1/rms
__device__ float g_wc[(size_t)MM*2*FF];   // wc  [4096,128]
__device__ float g_z[(size_t)MM*2*FF];    // rotated wc [4096,128]
__device__ float g_W2[(size_t)2*FF*DD];   // combined [Mre;-Mim] @ fwW^T  [128,1024]
__device__ float g_ct[(size_t)SS*FF];     // cos(s*pf[f])
__device__ float g_st[(size_t)SS*FF];     // sin(s*pf[f])

// ---------------- precompute: W2[j,d] ---------------------------------------
// mix[f] = exp(i*(speed*pi + phase)) * exp(-softplus(dampen))
// W2[f,d]    =  m*cos(th) * sum_g C[f,g]*fwW[d,g]
// W2[64+f,d] = -m*sin(th) * sum_g C[f,g]*fwW[d,g]
__global__ void k_prep_w2(const float* __restrict__ speed,
                          const float* __restrict__ dampen,
                          const float* __restrict__ phase,
                          const float* __restrict__ coupling,
                          const float* __restrict__ fwW) {
    int idx = blockIdx.x * blockDim.x + threadIdx.x;
    if (idx >= 2*FF*DD) return;
    int j = idx / DD, d = idx - j*DD;
    int f = j & (FF-1);
    float dmp = dampen[f];
    float sp  = (dmp > 20.f) ? dmp : log1pf(expf(dmp));   // softplus
    float m   = expf(-sp);
    float th  = speed[f] * CUDART_PI_F + phase[f];
    float c, s; sincosf(th, &s, &c);   // note: sincosf(x,&sin,&cos)
    float coef = (j < FF) ? (m * c) : (-m * s);
    float acc = 0.f;
    #pragma unroll 8
    for (int g = 0; g < FF; g++) acc += coupling[f*FF+g] * fwW[d*FF+g];
    g_W2[(size_t)j*DD + d] = coef * acc;
}

// ---------------- precompute: rotation tables -------------------------------
__global__ void k_tables(const float* __restrict__ pf) {
    int idx = blockIdx.x * blockDim.x + threadIdx.x;
    if (idx >= SS*FF) return;
    int s = idx / FF, f = idx - s*FF;
    float th = (float)s * pf[f];
    float sn, cs; sincosf(th, &sn, &cs);
    g_ct[idx] = cs;
    g_st[idx] = sn;
}

// ---------------- embedding gather ------------------------------------------
__global__ void k_embed(const int* __restrict__ tokens,
                        const float* __restrict__ embW) {
    int r = blockIdx.x;
    int t = tokens[r];
    const float4* src = (const float4*)(embW + (size_t)t * DD);
    float4* dst = (float4*)(g_x + (size_t)r * DD);
    dst[threadIdx.x] = src[threadIdx.x];   // 256 threads * float4 = 1024 floats
}

// ---------------- per-row rms ------------------------------------------------
__global__ void k_rms() {
    int r = blockIdx.x;
    int tid = threadIdx.x;
    const float4* row = (const float4*)(g_x + (size_t)r * DD);
    float4 v = row[tid];
    float ss = v.x*v.x + v.y*v.y + v.z*v.z + v.w*v.w;
    #pragma unroll
    for (int o = 16; o; o >>= 1) ss += __shfl_xor_sync(0xffffffffu, ss, o);
    __shared__ float red[8];
    if ((tid & 31) == 0) red[tid >> 5] = ss;
    __syncthreads();
    if (tid < 8) {
        float t = red[tid];
        #pragma unroll
        for (int o = 4; o; o >>= 1) t += __shfl_xor_sync(0xffu, t, o);
        if (tid == 0)
            g_rinv[r] = rsqrtf(t * (1.f/DD) + 1.1920929e-7f);  // eps = finfo(f32).eps
    }
}

// ---------------- GEMM1: wc = (x*rinv*nw) @ W1^T  [4096,1024]x[128,1024]^T --
// BM=32, BN=128(full), BK=32, 256 threads, 4x4 per thread
__global__ void __launch_bounds__(256) k_gemm1(const float* __restrict__ W1,
                                               const float* __restrict__ nw) {
    __shared__ __align__(16) float As[32][36];
    __shared__ __align__(16) float Bs[32][132];
    int tid = threadIdx.x;
    int r0 = blockIdx.x * 32;
    int tx = tid & 31, ty = tid >> 5;
    int arow = tid >> 3, akq = tid & 7;
    float ri = g_rinv[r0 + arow];
    float acc[4][4] = {};
    for (int k0 = 0; k0 < DD; k0 += 32) {
        float4 av  = *(const float4*)(g_x + (size_t)(r0+arow)*DD + k0 + akq*4);
        float4 nwv = *(const float4*)(nw + k0 + akq*4);
        As[akq*4+0][arow] = av.x * ri * nwv.x;
        As[akq*4+1][arow] = av.y * ri * nwv.y;
        As[akq*4+2][arow] = av.z * ri * nwv.z;
        As[akq*4+3][arow] = av.w * ri * nwv.w;
        #pragma unroll
        for (int l = 0; l < 4; l++) {
            int lin = tid + l*256;
            int brow = lin >> 3, bkq = lin & 7;
            float4 bv = *(const float4*)(W1 + (size_t)brow*DD + k0 + bkq*4);
            Bs[bkq*4+0][brow] = bv.x;
            Bs[bkq*4+1][brow] = bv.y;
            Bs[bkq*4+2][brow] = bv.z;
            Bs[bkq*4+3][brow] = bv.w;
        }
        __syncthreads();
        #pragma unroll
        for (int k = 0; k < 32; k++) {
            float a[4], b[4];
            #pragma unroll
            for (int i = 0; i < 4; i++) a[i] = As[k][ty*4+i];
            #pragma unroll
            for (int j = 0; j < 4; j++) b[j] = Bs[k][tx*4+j];
            #pragma unroll
            for (int i = 0; i < 4; i++)
                #pragma unroll
                for (int j = 0; j < 4; j++) acc[i][j] += a[i]*b[j];
        }
        __syncthreads();
    }
    #pragma unroll
    for (int i = 0; i < 4; i++)
        #pragma unroll
        for (int j = 0; j < 4; j++)
            g_wc[(size_t)(r0+ty*4+i)*128 + tx*4 + j] = acc[i][j];
}

// ---------------- rotation: z = Rot(s) * wc ---------------------------------
__global__ void k_rotate() {
    int idx = blockIdx.x * blockDim.x + threadIdx.x;
    if (idx >= MM*FF) return;
    int r = idx / FF, f = idx - r*FF;
    int s = r & (SS-1);
    float a = g_wc[(size_t)r*128 + f];
    float b = g_wc[(size_t)r*128 + FF + f];
    float c  = g_ct[(size_t)s*FF + f];
    float sn = g_st[(size_t)s*FF + f];
    g_z[(size_t)r*128 + f]      = a*c  - b*sn;
    g_z[(size_t)r*128 + FF + f] = a*sn + b*c;
}

// ---------------- GEMM2: x += alpha * (z @ W2)   [4096,128]x[128,1024] NN ---
// BM=32, BN=128, BK=32
__global__ void __launch_bounds__(256) k_gemm2(const float* __restrict__ step_scale,
                                               int t) {
    __shared__ __align__(16) float As[32][36];
    __shared__ __align__(16) float Bs[32][132];
    int tid = threadIdx.x;
    int r0 = blockIdx.y * 32;
    int n0 = blockIdx.x * 128;
    int tx = tid & 31, ty = tid >> 5;
    int arow = tid >> 3, akq = tid & 7;
    float acc[4][4] = {};
    for (int k0 = 0; k0 < 128; k0 += 32) {
        float4 av = *(const float4*)(g_z + (size_t)(r0+arow)*128 + k0 + akq*4);
        As[akq*4+0][arow] = av.x;
        As[akq*4+1][arow] = av.y;
        As[akq*4+2][arow] = av.z;
        As[akq*4+3][arow] = av.w;
        #pragma unroll
        for (int l = 0; l < 4; l++) {
            int lin = tid + l*256;
            int krow = lin >> 5, colq = lin & 31;
            float4 bv = *(const float4*)(g_W2 + (size_t)(k0+krow)*DD + n0 + colq*4);
            *(float4*)&Bs[krow][colq*4] = bv;
        }
        __syncthreads();
        #pragma unroll
        for (int k = 0; k < 32; k++) {
            float a[4], b[4];
            #pragma unroll
            for (int i = 0; i < 4; i++) a[i] = As[k][ty*4+i];
            #pragma unroll
            for (int j = 0; j < 4; j++) b[j] = Bs[k][tx*4+j];
            #pragma unroll
            for (int i = 0; i < 4; i++)
                #pragma unroll
                for (int j = 0; j < 4; j++) acc[i][j] += a[i]*b[j];
        }
        __syncthreads();
    }
    float alpha = 0.1f * step_scale[t];
    #pragma unroll
    for (int i = 0; i < 4; i++) {
        size_t rr = (size_t)(r0 + ty*4 + i) * DD + n0 + tx*4;
        #pragma unroll
        for (int j = 0; j < 4; j++)
            g_x[rr + j] += alpha * acc[i][j];
    }
}

// ---------------- lm_head: out = (x*rinv*onw) @ lmW^T  [4096,1024]x[V,1024]^T
// BM=128, BN=64, BK=16, 256 threads, 8x4 per thread
__global__ void __launch_bounds__(256) k_lm(const float* __restrict__ lmW,
                                            const float* __restrict__ onw,
                                            float* __restrict__ out) {
    __shared__ __align__(16) float As[16][132];
    __shared__ __align__(16) float Bs[16][68];
    int tid = threadIdx.x;
    int r0 = blockIdx.y * 128;
    int n0 = blockIdx.x * 64;
    int tx = tid & 15, ty = tid >> 4;
    int akq = tid & 3;
    int arow0 = tid >> 2;           // 0..63 ; also handles arow0+64
    float ri0 = g_rinv[r0 + arow0];
    float ri1 = g_rinv[r0 + arow0 + 64];
    float acc[8][4] = {};
    for (int k0 = 0; k0 < DD; k0 += 16) {
        float4 nwv = *(const float4*)(onw + k0 + akq*4);
        float4 a0 = *(const float4*)(g_x + (size_t)(r0+arow0)*DD    + k0 + akq*4);
        float4 a1 = *(const float4*)(g_x + (size_t)(r0+arow0+64)*DD + k0 + akq*4);
        As[akq*4+0][arow0] = a0.x * ri0 * nwv.x;
        As[akq*4+1][arow0] = a0.y * ri0 * nwv.y;
        As[akq*4+2][arow0] = a0.z * ri0 * nwv.z;
        As[akq*4+3][arow0] = a0.w * ri0 * nwv.w;
        As[akq*4+0][arow0+64] = a1.x * ri1 * nwv.x;
        As[akq*4+1][arow0+64] = a1.y * ri1 * nwv.y;
        As[akq*4+2][arow0+64] = a1.z * ri1 * nwv.z;
        As[akq*4+3][arow0+64] = a1.w * ri1 * nwv.w;
        int v = n0 + arow0;
        float4 bv = make_float4(0.f, 0.f, 0.f, 0.f);
        if (v < VV)
            bv = *(const float4*)(lmW + (size_t)v*DD + k0 + akq*4);
        Bs[akq*4+0][arow0] = bv.x;
        Bs[akq*4+1][arow0] = bv.y;
        Bs[akq*4+2][arow0] = bv.z;
        Bs[akq*4+3][arow0] = bv.w;
        __syncthreads();
        #pragma unroll
        for (int k = 0; k < 16; k++) {
            float a[8], b[4];
            #pragma unroll
            for (int i = 0; i < 8; i++) a[i] = As[k][ty*8+i];
            #pragma unroll
            for (int j = 0; j < 4; j++) b[j] = Bs[k][tx*4+j];
            #pragma unroll
            for (int i = 0; i < 8; i++)
                #pragma unroll
                for (int j = 0; j < 4; j++) acc[i][j] += a[i]*b[j];
        }
        __syncthreads();
    }
    #pragma unroll
    for (int i = 0; i < 8; i++) {
        size_t rr = (size_t)(r0 + ty*8 + i) * VV;
        #pragma unroll
        for (int j = 0; j < 4; j++) {
            int col = n0 + tx*4 + j;
            if (col < VV) out[rr + col] = acc[i][j];
        }
    }
}

// ---------------- launch -----------------------------------------------------
extern "C" void kernel_launch(void* const* d_in, const int* in_sizes, int n_in,
                              void* d_out, int out_size) {
    const int*   tokens   = (const int*)  d_in[0];
    const float* embW     = (const float*)d_in[1];
    const float* toW      = (const float*)d_in[2];   // [128,1024]
    const float* fwW      = (const float*)d_in[3];   // [1024,64]
    const float* speed    = (const float*)d_in[4];
    const float* dampen   = (const float*)d_in[5];
    const float* phase    = (const float*)d_in[6];
    const float* coupling = (const float*)d_in[7];
    const float* stepsc   = (const float*)d_in[8];
    const float* posf     = (const float*)d_in[9];
    const float* normsW   = (const float*)d_in[10];  // [28,1024]
    const float* onw      = (const float*)d_in[11];
    const float* lmW      = (const float*)d_in[12];  // [V,1024]
    float* out = (float*)d_out;

    k_prep_w2<<<(2*FF*DD + 255)/256, 256>>>(speed, dampen, phase, coupling, fwW);
    k_tables<<<(SS*FF + 255)/256, 256>>>(posf);
    k_embed<<<MM, 256>>>(tokens, embW);

    for (int t = 0; t < TT; t++) {
        k_rms<<<MM, 256>>>();
        k_gemm1<<<MM/32, 256>>>(toW, normsW + (size_t)t*DD);
        k_rotate<<<(MM*FF + 255)/256, 256>>>();
        k_gemm2<<<dim3(DD/128, MM/32), 256>>>(stepsc, t);
    }

    k_rms<<<MM, 256>>>();
    k_lm<<<dim3((VV + 63)/64, MM/128), 256>>>(lmW, onw, out);
}

// round 7
// speedup vs baseline: 1.8529x; 1.8529x over previous
#include <cuda_runtime.h>
#include <cuda_bf16.h>
#include <math.h>
#include <math_constants.h>
#include <cstdint>

#define BB 2
#define SS 2048
#define DD 1024
#define FF 64
#define TT 28
#define VV 50257
#define MM (BB*SS)      // 4096
#define NPAD 50432      // 197 * 256
#define KTOT 3072       // [ xh | xl | xh ]  vs  [ wh | wh | wl ]

// ==================== scratch (device globals; no allocation) ===============
__device__ float g_x[(size_t)MM*DD];
__device__ float g_rinv[MM];
__device__ float g_wc[(size_t)MM*2*FF];
__device__ float g_z[(size_t)MM*2*FF];
__device__ float g_W2[(size_t)2*FF*DD];
__device__ float g_ct[(size_t)SS*FF];
__device__ float g_st[(size_t)SS*FF];
// bf16 3-term split operands, concatenated along K
__device__ unsigned short g_Xs[(size_t)MM*KTOT];
__device__ unsigned short g_Ws[(size_t)NPAD*KTOT];

// ==================== helpers ===============================================
__device__ __forceinline__ uint32_t smem_u32(const void* p) {
    uint32_t a;
    asm("{ .reg .u64 t; cvta.to.shared.u64 t, %1; cvt.u32.u64 %0, t; }" : "=r"(a) : "l"(p));
    return a;
}
__device__ __forceinline__ void cp16(uint32_t dst, const void* src) {
    asm volatile("cp.async.cg.shared.global [%0], [%1], 16;\n" :: "r"(dst), "l"(src) : "memory");
}
__device__ __forceinline__ void cp_commit() { asm volatile("cp.async.commit_group;\n" ::: "memory"); }

__device__ __forceinline__ void ldm_x4(uint32_t* r, uint32_t addr) {
    asm volatile("ldmatrix.sync.aligned.m8n8.x4.shared.b16 {%0,%1,%2,%3}, [%4];"
        : "=r"(r[0]), "=r"(r[1]), "=r"(r[2]), "=r"(r[3]) : "r"(addr));
}
__device__ __forceinline__ void mma16816(float* d, const uint32_t* a, const uint32_t* b) {
    asm volatile("mma.sync.aligned.m16n8k16.row.col.f32.bf16.bf16.f32 "
        "{%0,%1,%2,%3}, {%4,%5,%6,%7}, {%8,%9}, {%0,%1,%2,%3};"
        : "+f"(d[0]), "+f"(d[1]), "+f"(d[2]), "+f"(d[3])
        : "r"(a[0]), "r"(a[1]), "r"(a[2]), "r"(a[3]), "r"(b[0]), "r"(b[1]));
}

// ==================== precompute W2 =========================================
__global__ void k_prep_w2(const float* __restrict__ speed,
                          const float* __restrict__ dampen,
                          const float* __restrict__ phase,
                          const float* __restrict__ coupling,
                          const float* __restrict__ fwW) {
    int idx = blockIdx.x * blockDim.x + threadIdx.x;
    if (idx >= 2*FF*DD) return;
    int j = idx / DD, d = idx - j*DD;
    int f = j & (FF-1);
    float dmp = dampen[f];
    float sp  = (dmp > 20.f) ? dmp : log1pf(expf(dmp));
    float m   = expf(-sp);
    float th  = speed[f] * CUDART_PI_F + phase[f];
    float c, s; sincosf(th, &s, &c);
    float coef = (j < FF) ? (m * c) : (-m * s);
    float acc = 0.f;
    #pragma unroll 8
    for (int g = 0; g < FF; g++) acc += coupling[f*FF+g] * fwW[d*FF+g];
    g_W2[(size_t)j*DD + d] = coef * acc;
}

__global__ void k_tables(const float* __restrict__ pf) {
    int idx = blockIdx.x * blockDim.x + threadIdx.x;
    if (idx >= SS*FF) return;
    int s = idx / FF, f = idx - s*FF;
    float th = (float)s * pf[f];
    float sn, cs; sincosf(th, &sn, &cs);
    g_ct[idx] = cs;
    g_st[idx] = sn;
}

__global__ void k_embed(const int* __restrict__ tokens,
                        const float* __restrict__ embW) {
    int r = blockIdx.x;
    int t = tokens[r];
    const float4* src = (const float4*)(embW + (size_t)t * DD);
    float4* dst = (float4*)(g_x + (size_t)r * DD);
    dst[threadIdx.x] = src[threadIdx.x];
}

__global__ void k_rms() {
    int r = blockIdx.x;
    int tid = threadIdx.x;
    const float4* row = (const float4*)(g_x + (size_t)r * DD);
    float4 v = row[tid];
    float ss = v.x*v.x + v.y*v.y + v.z*v.z + v.w*v.w;
    #pragma unroll
    for (int o = 16; o; o >>= 1) ss += __shfl_xor_sync(0xffffffffu, ss, o);
    __shared__ float red[8];
    if ((tid & 31) == 0) red[tid >> 5] = ss;
    __syncthreads();
    if (tid < 8) {
        float t = red[tid];
        #pragma unroll
        for (int o = 4; o; o >>= 1) t += __shfl_xor_sync(0xffu, t, o);
        if (tid == 0)
            g_rinv[r] = rsqrtf(t * (1.f/DD) + 1.1920929e-7f);
    }
}

// ==================== step-loop GEMMs (FMA-peak already) ====================
__global__ void __launch_bounds__(256) k_gemm1(const float* __restrict__ W1,
                                               const float* __restrict__ nw) {
    __shared__ __align__(16) float As[32][36];
    __shared__ __align__(16) float Bs[32][132];
    int tid = threadIdx.x;
    int r0 = blockIdx.x * 32;
    int tx = tid & 31, ty = tid >> 5;
    int arow = tid >> 3, akq = tid & 7;
    float ri = g_rinv[r0 + arow];
    float acc[4][4] = {};
    for (int k0 = 0; k0 < DD; k0 += 32) {
        float4 av  = *(const float4*)(g_x + (size_t)(r0+arow)*DD + k0 + akq*4);
        float4 nwv = *(const float4*)(nw + k0 + akq*4);
        As[akq*4+0][arow] = av.x * ri * nwv.x;
        As[akq*4+1][arow] = av.y * ri * nwv.y;
        As[akq*4+2][arow] = av.z * ri * nwv.z;
        As[akq*4+3][arow] = av.w * ri * nwv.w;
        #pragma unroll
        for (int l = 0; l < 4; l++) {
            int lin = tid + l*256;
            int brow = lin >> 3, bkq = lin & 7;
            float4 bv = *(const float4*)(W1 + (size_t)brow*DD + k0 + bkq*4);
            Bs[bkq*4+0][brow] = bv.x;
            Bs[bkq*4+1][brow] = bv.y;
            Bs[bkq*4+2][brow] = bv.z;
            Bs[bkq*4+3][brow] = bv.w;
        }
        __syncthreads();
        #pragma unroll
        for (int k = 0; k < 32; k++) {
            float a[4], b[4];
            #pragma unroll
            for (int i = 0; i < 4; i++) a[i] = As[k][ty*4+i];
            #pragma unroll
            for (int j = 0; j < 4; j++) b[j] = Bs[k][tx*4+j];
            #pragma unroll
            for (int i = 0; i < 4; i++)
                #pragma unroll
                for (int j = 0; j < 4; j++) acc[i][j] += a[i]*b[j];
        }
        __syncthreads();
    }
    #pragma unroll
    for (int i = 0; i < 4; i++)
        #pragma unroll
        for (int j = 0; j < 4; j++)
            g_wc[(size_t)(r0+ty*4+i)*128 + tx*4 + j] = acc[i][j];
}

__global__ void k_rotate() {
    int idx = blockIdx.x * blockDim.x + threadIdx.x;
    if (idx >= MM*FF) return;
    int r = idx / FF, f = idx - r*FF;
    int s = r & (SS-1);
    float a = g_wc[(size_t)r*128 + f];
    float b = g_wc[(size_t)r*128 + FF + f];
    float c  = g_ct[(size_t)s*FF + f];
    float sn = g_st[(size_t)s*FF + f];
    g_z[(size_t)r*128 + f]      = a*c  - b*sn;
    g_z[(size_t)r*128 + FF + f] = a*sn + b*c;
}

__global__ void __launch_bounds__(256) k_gemm2(const float* __restrict__ step_scale,
                                               int t) {
    __shared__ __align__(16) float As[32][36];
    __shared__ __align__(16) float Bs[32][132];
    int tid = threadIdx.x;
    int r0 = blockIdx.y * 32;
    int n0 = blockIdx.x * 128;
    int tx = tid & 31, ty = tid >> 5;
    int arow = tid >> 3, akq = tid & 7;
    float acc[4][4] = {};
    for (int k0 = 0; k0 < 128; k0 += 32) {
        float4 av = *(const float4*)(g_z + (size_t)(r0+arow)*128 + k0 + akq*4);
        As[akq*4+0][arow] = av.x;
        As[akq*4+1][arow] = av.y;
        As[akq*4+2][arow] = av.z;
        As[akq*4+3][arow] = av.w;
        #pragma unroll
        for (int l = 0; l < 4; l++) {
            int lin = tid + l*256;
            int krow = lin >> 5, colq = lin & 31;
            float4 bv = *(const float4*)(g_W2 + (size_t)(k0+krow)*DD + n0 + colq*4);
            *(float4*)&Bs[krow][colq*4] = bv;
        }
        __syncthreads();
        #pragma unroll
        for (int k = 0; k < 32; k++) {
            float a[4], b[4];
            #pragma unroll
            for (int i = 0; i < 4; i++) a[i] = As[k][ty*4+i];
            #pragma unroll
            for (int j = 0; j < 4; j++) b[j] = Bs[k][tx*4+j];
            #pragma unroll
            for (int i = 0; i < 4; i++)
                #pragma unroll
                for (int j = 0; j < 4; j++) acc[i][j] += a[i]*b[j];
        }
        __syncthreads();
    }
    float alpha = 0.1f * step_scale[t];
    #pragma unroll
    for (int i = 0; i < 4; i++) {
        size_t rr = (size_t)(r0 + ty*4 + i) * DD + n0 + tx*4;
        #pragma unroll
        for (int j = 0; j < 4; j++)
            g_x[rr + j] += alpha * acc[i][j];
    }
}

// ==================== bf16 3-term split conversions =========================
// Ws row layout: [ wh (0..1023) | wh (1024..2047) | wl (2048..3071) ]
__global__ void k_convW(const float* __restrict__ lmW) {
    int v = blockIdx.x;           // 0 .. NPAD-1
    int tid = threadIdx.x;        // 256 threads * 4 elems
    float4 w = make_float4(0.f, 0.f, 0.f, 0.f);
    if (v < VV) w = *(const float4*)(lmW + (size_t)v*DD + tid*4);
    __nv_bfloat16 h0 = __float2bfloat16_rn(w.x);
    __nv_bfloat16 h1 = __float2bfloat16_rn(w.y);
    __nv_bfloat16 h2 = __float2bfloat16_rn(w.z);
    __nv_bfloat16 h3 = __float2bfloat16_rn(w.w);
    __nv_bfloat16 l0 = __float2bfloat16_rn(w.x - __bfloat162float(h0));
    __nv_bfloat16 l1 = __float2bfloat16_rn(w.y - __bfloat162float(h1));
    __nv_bfloat16 l2 = __float2bfloat16_rn(w.z - __bfloat162float(h2));
    __nv_bfloat16 l3 = __float2bfloat16_rn(w.w - __bfloat162float(h3));
    size_t base = (size_t)v*KTOT;
    __nv_bfloat162 hA{h0, h1}, hB{h2, h3};
    __nv_bfloat162 lA{l0, l1}, lB{l2, l3};
    __nv_bfloat162* p0 = (__nv_bfloat162*)(g_Ws + base + tid*4);
    __nv_bfloat162* p1 = (__nv_bfloat162*)(g_Ws + base + 1024 + tid*4);
    __nv_bfloat162* p2 = (__nv_bfloat162*)(g_Ws + base + 2048 + tid*4);
    p0[0] = hA; p0[1] = hB;      // wh
    p1[0] = hA; p1[1] = hB;      // wh (pairs with xl)
    p2[0] = lA; p2[1] = lB;      // wl (pairs with xh)
}

// Xs row layout: [ xh (0..1023) | xl (1024..2047) | xh (2048..3071) ]
__global__ void k_convX(const float* __restrict__ onw) {
    int r = blockIdx.x;
    int tid = threadIdx.x;
    float ri = g_rinv[r];
    float4 xv = *(const float4*)(g_x + (size_t)r*DD + tid*4);
    float4 nw = *(const float4*)(onw + tid*4);
    float a0 = xv.x * ri * nw.x, a1 = xv.y * ri * nw.y;
    float a2 = xv.z * ri * nw.z, a3 = xv.w * ri * nw.w;
    __nv_bfloat16 h0 = __float2bfloat16_rn(a0);
    __nv_bfloat16 h1 = __float2bfloat16_rn(a1);
    __nv_bfloat16 h2 = __float2bfloat16_rn(a2);
    __nv_bfloat16 h3 = __float2bfloat16_rn(a3);
    __nv_bfloat16 l0 = __float2bfloat16_rn(a0 - __bfloat162float(h0));
    __nv_bfloat16 l1 = __float2bfloat16_rn(a1 - __bfloat162float(h1));
    __nv_bfloat16 l2 = __float2bfloat16_rn(a2 - __bfloat162float(h2));
    __nv_bfloat16 l3 = __float2bfloat16_rn(a3 - __bfloat162float(h3));
    size_t base = (size_t)r*KTOT;
    __nv_bfloat162 hA{h0, h1}, hB{h2, h3};
    __nv_bfloat162 lA{l0, l1}, lB{l2, l3};
    __nv_bfloat162* p0 = (__nv_bfloat162*)(g_Xs + base + tid*4);
    __nv_bfloat162* p1 = (__nv_bfloat162*)(g_Xs + base + 1024 + tid*4);
    __nv_bfloat162* p2 = (__nv_bfloat162*)(g_Xs + base + 2048 + tid*4);
    p0[0] = hA; p0[1] = hB;      // xh
    p1[0] = lA; p1[1] = lB;      // xl
    p2[0] = hA; p2[1] = hB;      // xh
}

// ==================== mma.sync lm_head GEMM =================================
// out[4096, 50257] = Xs @ Ws^T over K=3072:
//   Sum = xh.wh + xl.wh + xh.wl  =  x.w - xl.wl (~2^-18) -> rel_err ~1e-5.
// BM=128, BN=256, BK=64 (128B swizzled rows), 512 threads, 3-stage cp.async.
#define STAGE_SZ 49152       // A 16K + B 32K
#define NSTG 3
#define NITK (KTOT/64)       // 48

__global__ void __launch_bounds__(512, 1) k_lm_mma(float* __restrict__ out) {
    extern __shared__ __align__(128) char smem[];
    uint32_t sb = smem_u32(smem);
    int tid = threadIdx.x;
    int lane = tid & 31, wid = tid >> 5;
    int warp_m = wid & 3, warp_n = wid >> 2;
    int r0 = blockIdx.x * 128;      // M fastest: A stays L2-resident, B streams once
    int n0 = blockIdx.y * 256;

    const char* srcA = (const char*)g_Xs + ((size_t)r0 * KTOT) * 2;
    const char* srcB = (const char*)g_Ws + ((size_t)n0 * KTOT) * 2;

    int lrow = ((lane >> 3) & 1) * 8 + (lane & 7);
    int uadd = lane >> 4;
    int rA = warp_m * 32 + lrow;
    int rB = warp_n * 64 + lrow;
    int sA = rA & 7, sB = rB & 7;
    uint32_t aBase = sb + rA * 128;
    uint32_t bBase = sb + 16384 + rB * 128;

    float acc[2][8][4];
    #pragma unroll
    for (int mt = 0; mt < 2; mt++)
        #pragma unroll
        for (int nr = 0; nr < 8; nr++)
            #pragma unroll
            for (int q = 0; q < 4; q++) acc[mt][nr][q] = 0.f;

    auto issue = [&](int kt, int stg) {
        uint32_t st = sb + stg * STAGE_SZ;
        #pragma unroll
        for (int j = 0; j < 2; j++) {           // A: 128 rows x 8 units
            int idx = tid + j*512;
            int row = idx >> 3, u = idx & 7;
            cp16(st + row*128 + ((u ^ (row & 7)) << 4),
                 srcA + ((size_t)row*KTOT + kt*64 + u*8) * 2);
        }
        #pragma unroll
        for (int j = 0; j < 4; j++) {           // B: 256 rows x 8 units
            int idx = tid + j*512;
            int row = idx >> 3, u = idx & 7;
            cp16(st + 16384 + row*128 + ((u ^ (row & 7)) << 4),
                 srcB + ((size_t)row*KTOT + kt*64 + u*8) * 2);
        }
        cp_commit();
    };

    issue(0, 0);
    issue(1, 1);

    for (int kt = 0; kt < NITK; kt++) {
        if (kt < NITK - 1) asm volatile("cp.async.wait_group 1;" ::: "memory");
        else               asm volatile("cp.async.wait_group 0;" ::: "memory");
        __syncthreads();
        if (kt + 2 < NITK) issue(kt + 2, (kt + 2) % NSTG);

        int stg = kt % NSTG;
        uint32_t stA = aBase + stg * STAGE_SZ;
        uint32_t stB = bBase + stg * STAGE_SZ;
        #pragma unroll
        for (int kk = 0; kk < 4; kk++) {
            uint32_t af[2][4], bf[4][4];
            #pragma unroll
            for (int mt = 0; mt < 2; mt++)
                ldm_x4(af[mt], stA + mt*2048 + (((kk*2 + uadd) ^ sA) << 4));
            #pragma unroll
            for (int nt = 0; nt < 4; nt++)
                ldm_x4(bf[nt], stB + nt*2048 + (((kk*2 + uadd) ^ sB) << 4));
            #pragma unroll
            for (int mt = 0; mt < 2; mt++)
                #pragma unroll
                for (int nr = 0; nr < 8; nr++) {
                    uint32_t b2[2] = { bf[nr>>1][nr & 1], bf[nr>>1][(nr & 1) + 2] };
                    mma16816(acc[mt][nr], af[mt], b2);
                }
        }
        __syncthreads();
    }

    // ---- epilogue: direct fragment stores ---------------------------------
    int orow = r0 + warp_m*32 + (lane >> 2);
    int ocol = n0 + warp_n*64 + (lane & 3)*2;
    #pragma unroll
    for (int mt = 0; mt < 2; mt++) {
        #pragma unroll
        for (int nr = 0; nr < 8; nr++) {
            int cc = ocol + (nr >> 1)*16 + (nr & 1)*8;
            size_t p0 = (size_t)(orow + mt*16)     * VV + cc;
            size_t p1 = (size_t)(orow + mt*16 + 8) * VV + cc;
            if (cc < VV)     { out[p0]   = acc[mt][nr][0]; out[p1]   = acc[mt][nr][2]; }
            if (cc + 1 < VV) { out[p0+1] = acc[mt][nr][1]; out[p1+1] = acc[mt][nr][3]; }
        }
    }
}

// ==================== launch ================================================
extern "C" void kernel_launch(void* const* d_in, const int* in_sizes, int n_in,
                              void* d_out, int out_size) {
    const int*   tokens   = (const int*)  d_in[0];
    const float* embW     = (const float*)d_in[1];
    const float* toW      = (const float*)d_in[2];
    const float* fwW      = (const float*)d_in[3];
    const float* speed    = (const float*)d_in[4];
    const float* dampen   = (const float*)d_in[5];
    const float* phase    = (const float*)d_in[6];
    const float* coupling = (const float*)d_in[7];
    const float* stepsc   = (const float*)d_in[8];
    const float* posf     = (const float*)d_in[9];
    const float* normsW   = (const float*)d_in[10];
    const float* onw      = (const float*)d_in[11];
    const float* lmW      = (const float*)d_in[12];
    float* out = (float*)d_out;

    cudaFuncSetAttribute(k_lm_mma, cudaFuncAttributeMaxDynamicSharedMemorySize,
                         NSTG * STAGE_SZ);

    k_prep_w2<<<(2*FF*DD + 255)/256, 256>>>(speed, dampen, phase, coupling, fwW);
    k_tables<<<(SS*FF + 255)/256, 256>>>(posf);
    k_embed<<<MM, 256>>>(tokens, embW);
    k_convW<<<NPAD, 256>>>(lmW);

    for (int t = 0; t < TT; t++) {
        k_rms<<<MM, 256>>>();
        k_gemm1<<<MM/32, 256>>>(toW, normsW + (size_t)t*DD);
        k_rotate<<<(MM*FF + 255)/256, 256>>>();
        k_gemm2<<<dim3(DD/128, MM/32), 256>>>(stepsc, t);
    }

    k_rms<<<MM, 256>>>();
    k_convX<<<MM, 256>>>(onw);
    k_lm_mma<<<dim3(MM/128, NPAD/256), 512, NSTG*STAGE_SZ>>>(out);
}

// round 8
// speedup vs baseline: 2.2087x; 1.1921x over previous
#include <cuda_runtime.h>
#include <cuda_bf16.h>
#include <math.h>
#include <math_constants.h>
#include <cstdint>

#define BB 2
#define SS 2048
#define DD 1024
#define FF 64
#define TT 28
#define VV 50257
#define MM (BB*SS)      // 4096
#define NPAD 50432      // 197 * 256
#define KTOT 3072       // lm split: [ xh | xl | xh ] vs [ wh | wh | wl ]
#define K1   3072       // gemm1 split K (D=1024 * 3)
#define K2   384        // gemm2 split K (2F=128 * 3)

// ==================== scratch (device globals; no allocation) ===============
__device__ float g_x[(size_t)MM*DD];
__device__ float g_wc[(size_t)MM*2*FF];
__device__ float g_ct[(size_t)SS*FF];
__device__ float g_st[(size_t)SS*FF];
__device__ unsigned short g_Xs[(size_t)MM*KTOT];    // split x (step gemm1 + lm A)
__device__ unsigned short g_Ws[(size_t)NPAD*KTOT];  // split lm_head W
__device__ unsigned short g_W1s[(size_t)2*FF*K1];   // split to_wave_W  [128,3072]
__device__ unsigned short g_W2s[(size_t)DD*K2];     // split W2^T      [1024,384]
__device__ unsigned short g_Zs[(size_t)MM*K2];      // split rotated z [4096,384]

// ==================== helpers ===============================================
__device__ __forceinline__ uint32_t smem_u32(const void* p) {
    uint32_t a;
    asm("{ .reg .u64 t; cvta.to.shared.u64 t, %1; cvt.u32.u64 %0, t; }" : "=r"(a) : "l"(p));
    return a;
}
__device__ __forceinline__ void cp16(uint32_t dst, const void* src) {
    asm volatile("cp.async.cg.shared.global [%0], [%1], 16;\n" :: "r"(dst), "l"(src) : "memory");
}
__device__ __forceinline__ void cp_commit() { asm volatile("cp.async.commit_group;\n" ::: "memory"); }

__device__ __forceinline__ void ldm_x4(uint32_t* r, uint32_t addr) {
    asm volatile("ldmatrix.sync.aligned.m8n8.x4.shared.b16 {%0,%1,%2,%3}, [%4];"
        : "=r"(r[0]), "=r"(r[1]), "=r"(r[2]), "=r"(r[3]) : "r"(addr));
}
__device__ __forceinline__ void mma16816(float* d, const uint32_t* a, const uint32_t* b) {
    asm volatile("mma.sync.aligned.m16n8k16.row.col.f32.bf16.bf16.f32 "
        "{%0,%1,%2,%3}, {%4,%5,%6,%7}, {%8,%9}, {%0,%1,%2,%3};"
        : "+f"(d[0]), "+f"(d[1]), "+f"(d[2]), "+f"(d[3])
        : "r"(a[0]), "r"(a[1]), "r"(a[2]), "r"(a[3]), "r"(b[0]), "r"(b[1]));
}
__device__ __forceinline__ void split2(float v, __nv_bfloat16& h, __nv_bfloat16& l) {
    h = __float2bfloat16_rn(v);
    l = __float2bfloat16_rn(v - __bfloat162float(h));
}

// ==================== one-time precompute ===================================
// W2[j,d] = coef(j) * sum_g C[f,g]*fwW[d,g]; store split-transposed:
// W2s[d][j]=hi, W2s[d][128+j]=hi, W2s[d][256+j]=lo  (pairs with z=[zh|zl|zh])
__global__ void k_prep_w2s(const float* __restrict__ speed,
                           const float* __restrict__ dampen,
                           const float* __restrict__ phase,
                           const float* __restrict__ coupling,
                           const float* __restrict__ fwW) {
    int idx = blockIdx.x * blockDim.x + threadIdx.x;   // d*128 + j (coalesced writes)
    if (idx >= DD*2*FF) return;
    int d = idx >> 7, j = idx & 127;
    int f = j & (FF-1);
    float dmp = dampen[f];
    float sp  = (dmp > 20.f) ? dmp : log1pf(expf(dmp));
    float m   = expf(-sp);
    float th  = speed[f] * CUDART_PI_F + phase[f];
    float c, s; sincosf(th, &s, &c);
    float coef = (j < FF) ? (m * c) : (-m * s);
    float acc = 0.f;
    #pragma unroll 8
    for (int g = 0; g < FF; g++) acc += coupling[f*FF+g] * fwW[d*FF+g];
    float v = coef * acc;
    __nv_bfloat16 h, l; split2(v, h, l);
    __nv_bfloat16* W = (__nv_bfloat16*)(g_W2s + (size_t)d*K2);
    W[j] = h; W[128+j] = h; W[256+j] = l;
}

// to_wave_W [128,1024] -> W1s [128, 3072] = [wh|wh|wl]
__global__ void k_convW1(const float* __restrict__ toW) {
    int f = blockIdx.x;           // 0..127
    int tid = threadIdx.x;        // 256 threads * 4 elems
    float4 w = *(const float4*)(toW + (size_t)f*DD + tid*4);
    __nv_bfloat16 h0,h1,h2,h3,l0,l1,l2,l3;
    split2(w.x,h0,l0); split2(w.y,h1,l1); split2(w.z,h2,l2); split2(w.w,h3,l3);
    size_t base = (size_t)f*K1;
    __nv_bfloat162 hA{h0,h1}, hB{h2,h3}, lA{l0,l1}, lB{l2,l3};
    __nv_bfloat162* p0 = (__nv_bfloat162*)(g_W1s + base + tid*4);
    __nv_bfloat162* p1 = (__nv_bfloat162*)(g_W1s + base + 1024 + tid*4);
    __nv_bfloat162* p2 = (__nv_bfloat162*)(g_W1s + base + 2048 + tid*4);
    p0[0]=hA; p0[1]=hB;  p1[0]=hA; p1[1]=hB;  p2[0]=lA; p2[1]=lB;
}

__global__ void k_tables(const float* __restrict__ pf) {
    int idx = blockIdx.x * blockDim.x + threadIdx.x;
    if (idx >= SS*FF) return;
    int s = idx / FF, f = idx - s*FF;
    float th = (float)s * pf[f];
    float sn, cs; sincosf(th, &sn, &cs);
    g_ct[idx] = cs;
    g_st[idx] = sn;
}

__global__ void k_embed(const int* __restrict__ tokens,
                        const float* __restrict__ embW) {
    int r = blockIdx.x;
    int t = tokens[r];
    const float4* src = (const float4*)(embW + (size_t)t * DD);
    float4* dst = (float4*)(g_x + (size_t)r * DD);
    dst[threadIdx.x] = src[threadIdx.x];
}

// lm_head W [V,1024] -> Ws [NPAD, 3072] = [wh|wh|wl]
__global__ void k_convW(const float* __restrict__ lmW) {
    int v = blockIdx.x;           // 0 .. NPAD-1
    int tid = threadIdx.x;
    float4 w = make_float4(0.f, 0.f, 0.f, 0.f);
    if (v < VV) w = *(const float4*)(lmW + (size_t)v*DD + tid*4);
    __nv_bfloat16 h0,h1,h2,h3,l0,l1,l2,l3;
    split2(w.x,h0,l0); split2(w.y,h1,l1); split2(w.z,h2,l2); split2(w.w,h3,l3);
    size_t base = (size_t)v*KTOT;
    __nv_bfloat162 hA{h0,h1}, hB{h2,h3}, lA{l0,l1}, lB{l2,l3};
    __nv_bfloat162* p0 = (__nv_bfloat162*)(g_Ws + base + tid*4);
    __nv_bfloat162* p1 = (__nv_bfloat162*)(g_Ws + base + 1024 + tid*4);
    __nv_bfloat162* p2 = (__nv_bfloat162*)(g_Ws + base + 2048 + tid*4);
    p0[0]=hA; p0[1]=hB;  p1[0]=hA; p1[1]=hB;  p2[0]=lA; p2[1]=lB;
}

// ==================== fused rmsnorm + split-convert =========================
// g_Xs[r] = split( x[r] * rinv(x[r]) * nw )  as [xh|xl|xh]
__global__ void k_rmsconv(const float* __restrict__ nw) {
    int r = blockIdx.x;
    int tid = threadIdx.x;
    float4 v = ((const float4*)(g_x + (size_t)r*DD))[tid];
    float ss = v.x*v.x + v.y*v.y + v.z*v.z + v.w*v.w;
    #pragma unroll
    for (int o = 16; o; o >>= 1) ss += __shfl_xor_sync(0xffffffffu, ss, o);
    __shared__ float red[8];
    __shared__ float s_rinv;
    if ((tid & 31) == 0) red[tid >> 5] = ss;
    __syncthreads();
    if (tid < 8) {
        float t = red[tid];
        #pragma unroll
        for (int o = 4; o; o >>= 1) t += __shfl_xor_sync(0xffu, t, o);
        if (tid == 0) s_rinv = rsqrtf(t * (1.f/DD) + 1.1920929e-7f);
    }
    __syncthreads();
    float ri = s_rinv;
    float4 nwv = ((const float4*)nw)[tid];
    float a0 = v.x*ri*nwv.x, a1 = v.y*ri*nwv.y, a2 = v.z*ri*nwv.z, a3 = v.w*ri*nwv.w;
    __nv_bfloat16 h0,h1,h2,h3,l0,l1,l2,l3;
    split2(a0,h0,l0); split2(a1,h1,l1); split2(a2,h2,l2); split2(a3,h3,l3);
    size_t base = (size_t)r*KTOT;
    __nv_bfloat162 hA{h0,h1}, hB{h2,h3}, lA{l0,l1}, lB{l2,l3};
    __nv_bfloat162* p0 = (__nv_bfloat162*)(g_Xs + base + tid*4);
    __nv_bfloat162* p1 = (__nv_bfloat162*)(g_Xs + base + 1024 + tid*4);
    __nv_bfloat162* p2 = (__nv_bfloat162*)(g_Xs + base + 2048 + tid*4);
    p0[0]=hA; p0[1]=hB;  p1[0]=lA; p1[1]=lB;  p2[0]=hA; p2[1]=hB;
}

// ==================== gemm1 (mma): wc = Xs @ W1s^T ==========================
// [4096,3072] x [128,3072]^T -> fp32 [4096,128].  BM=64 BN=128 BK=64,
// 256 thr (8 warps: 4 warp_m x 2 warp_n, warp tile 16x64), 3-stage cp.async.
#define G1_STG 24576        // A 8K + B 16K
__global__ void __launch_bounds__(256, 1) k_gemm1_mma() {
    extern __shared__ __align__(128) char smem[];
    uint32_t sb = smem_u32(smem);
    int tid = threadIdx.x, lane = tid & 31, wid = tid >> 5;
    int warp_m = wid & 3, warp_n = wid >> 2;
    int r0 = blockIdx.x * 64;
    const char* srcA = (const char*)g_Xs + ((size_t)r0 * K1) * 2;
    const char* srcB = (const char*)g_W1s;
    int lrow = ((lane >> 3) & 1) * 8 + (lane & 7);
    int uadd = lane >> 4;
    int rA = warp_m*16 + lrow;
    int rB = warp_n*64 + lrow;
    int sA = rA & 7, sB = rB & 7;
    uint32_t aBase = sb + rA*128;
    uint32_t bBase = sb + 8192 + rB*128;
    float acc[8][4] = {};

    auto issue = [&](int kt, int stg) {
        uint32_t st = sb + stg*G1_STG;
        #pragma unroll
        for (int j = 0; j < 2; j++) {           // A: 64 rows x 8 units
            int idx = tid + j*256; int row = idx >> 3, u = idx & 7;
            cp16(st + row*128 + ((u ^ (row & 7)) << 4),
                 srcA + ((size_t)row*K1 + kt*64 + u*8) * 2);
        }
        #pragma unroll
        for (int j = 0; j < 4; j++) {           // B: 128 rows x 8 units
            int idx = tid + j*256; int row = idx >> 3, u = idx & 7;
            cp16(st + 8192 + row*128 + ((u ^ (row & 7)) << 4),
                 srcB + ((size_t)row*K1 + kt*64 + u*8) * 2);
        }
        cp_commit();
    };
    issue(0, 0); issue(1, 1);
    const int NIT = K1/64;   // 48
    for (int kt = 0; kt < NIT; kt++) {
        if (kt < NIT-1) asm volatile("cp.async.wait_group 1;" ::: "memory");
        else            asm volatile("cp.async.wait_group 0;" ::: "memory");
        __syncthreads();
        if (kt + 2 < NIT) issue(kt + 2, (kt + 2) % 3);
        uint32_t stA = aBase + (kt % 3)*G1_STG;
        uint32_t stB = bBase + (kt % 3)*G1_STG;
        #pragma unroll
        for (int kk = 0; kk < 4; kk++) {
            uint32_t af[4], bf[4][4];
            ldm_x4(af, stA + (((kk*2 + uadd) ^ sA) << 4));
            #pragma unroll
            for (int nt = 0; nt < 4; nt++)
                ldm_x4(bf[nt], stB + nt*2048 + (((kk*2 + uadd) ^ sB) << 4));
            #pragma unroll
            for (int nr = 0; nr < 8; nr++) {
                uint32_t b2[2] = { bf[nr>>1][nr & 1], bf[nr>>1][(nr & 1) + 2] };
                mma16816(acc[nr], af, b2);
            }
        }
        __syncthreads();
    }
    int orow = r0 + warp_m*16 + (lane >> 2);
    int ocol = warp_n*64 + (lane & 3)*2;
    #pragma unroll
    for (int nr = 0; nr < 8; nr++) {
        int cc = ocol + (nr >> 1)*16 + (nr & 1)*8;
        size_t p0 = (size_t)orow*128 + cc;
        size_t p1 = (size_t)(orow + 8)*128 + cc;
        g_wc[p0] = acc[nr][0]; g_wc[p0+1] = acc[nr][1];
        g_wc[p1] = acc[nr][2]; g_wc[p1+1] = acc[nr][3];
    }
}

// ==================== rotate + split-convert z ==============================
__global__ void k_convZ() {
    int rr = blockIdx.x*2 + (threadIdx.x >> 6);
    int f  = threadIdx.x & 63;
    float a = g_wc[(size_t)rr*128 + f];
    float b = g_wc[(size_t)rr*128 + 64 + f];
    int s = rr & (SS-1);
    float ct = g_ct[(size_t)s*FF + f];
    float st = g_st[(size_t)s*FF + f];
    float zr = a*ct - b*st;
    float zi = a*st + b*ct;
    __nv_bfloat16 rh, rl, ih, il;
    split2(zr, rh, rl); split2(zi, ih, il);
    __nv_bfloat16* Z = (__nv_bfloat16*)(g_Zs + (size_t)rr*K2);
    Z[f] = rh;  Z[64+f] = ih;          // [zh]
    Z[128+f] = rl; Z[192+f] = il;      // [zl]
    Z[256+f] = rh; Z[320+f] = ih;      // [zh]
}

// ==================== gemm2 (mma): x += alpha * Zs @ W2s^T ==================
// [4096,384] x [1024,384]^T.  BM=128 BN=128 BK=64, 256 thr
// (4 warp_m x 2 warp_n, warp tile 32x64), 3-stage cp.async, 6 k-iters.
#define G2_STG 32768        // A 16K + B 16K
__global__ void __launch_bounds__(256, 1) k_gemm2_mma(const float* __restrict__ step_scale,
                                                      int t) {
    extern __shared__ __align__(128) char smem[];
    uint32_t sb = smem_u32(smem);
    int tid = threadIdx.x, lane = tid & 31, wid = tid >> 5;
    int warp_m = wid & 3, warp_n = wid >> 2;
    int r0 = blockIdx.y * 128;
    int n0 = blockIdx.x * 128;
    const char* srcA = (const char*)g_Zs  + ((size_t)r0 * K2) * 2;
    const char* srcB = (const char*)g_W2s + ((size_t)n0 * K2) * 2;
    int lrow = ((lane >> 3) & 1) * 8 + (lane & 7);
    int uadd = lane >> 4;
    int rA = warp_m*32 + lrow;
    int rB = warp_n*64 + lrow;
    int sA = rA & 7, sB = rB & 7;
    uint32_t aBase = sb + rA*128;
    uint32_t bBase = sb + 16384 + rB*128;
    float acc[2][8][4] = {};

    auto issue = [&](int kt, int stg) {
        uint32_t st = sb + stg*G2_STG;
        #pragma unroll
        for (int j = 0; j < 4; j++) {           // A: 128 rows x 8 units
            int idx = tid + j*256; int row = idx >> 3, u = idx & 7;
            cp16(st + row*128 + ((u ^ (row & 7)) << 4),
                 srcA + ((size_t)row*K2 + kt*64 + u*8) * 2);
        }
        #pragma unroll
        for (int j = 0; j < 4; j++) {           // B: 128 rows x 8 units
            int idx = tid + j*256; int row = idx >> 3, u = idx & 7;
            cp16(st + 16384 + row*128 + ((u ^ (row & 7)) << 4),
                 srcB + ((size_t)row*K2 + kt*64 + u*8) * 2);
        }
        cp_commit();
    };
    issue(0, 0); issue(1, 1);
    const int NIT = K2/64;   // 6
    for (int kt = 0; kt < NIT; kt++) {
        if (kt < NIT-1) asm volatile("cp.async.wait_group 1;" ::: "memory");
        else            asm volatile("cp.async.wait_group 0;" ::: "memory");
        __syncthreads();
        if (kt + 2 < NIT) issue(kt + 2, (kt + 2) % 3);
        uint32_t stA = aBase + (kt % 3)*G2_STG;
        uint32_t stB = bBase + (kt % 3)*G2_STG;
        #pragma unroll
        for (int kk = 0; kk < 4; kk++) {
            uint32_t af[2][4], bf[4][4];
            #pragma unroll
            for (int mt = 0; mt < 2; mt++)
                ldm_x4(af[mt], stA + mt*2048 + (((kk*2 + uadd) ^ sA) << 4));
            #pragma unroll
            for (int nt = 0; nt < 4; nt++)
                ldm_x4(bf[nt], stB + nt*2048 + (((kk*2 + uadd) ^ sB) << 4));
            #pragma unroll
            for (int mt = 0; mt < 2; mt++)
                #pragma unroll
                for (int nr = 0; nr < 8; nr++) {
                    uint32_t b2[2] = { bf[nr>>1][nr & 1], bf[nr>>1][(nr & 1) + 2] };
                    mma16816(acc[mt][nr], af[mt], b2);
                }
        }
        __syncthreads();
    }
    float alpha = 0.1f * step_scale[t];
    int orow = r0 + warp_m*32 + (lane >> 2);
    int ocol = n0 + warp_n*64 + (lane & 3)*2;
    #pragma unroll
    for (int mt = 0; mt < 2; mt++) {
        #pragma unroll
        for (int nr = 0; nr < 8; nr++) {
            int cc = ocol + (nr >> 1)*16 + (nr & 1)*8;
            size_t p0 = (size_t)(orow + mt*16)     * DD + cc;
            size_t p1 = (size_t)(orow + mt*16 + 8) * DD + cc;
            g_x[p0]   += alpha*acc[mt][nr][0]; g_x[p0+1] += alpha*acc[mt][nr][1];
            g_x[p1]   += alpha*acc[mt][nr][2]; g_x[p1+1] += alpha*acc[mt][nr][3];
        }
    }
}

// ==================== mma.sync lm_head GEMM (4-stage) =======================
#define STAGE_SZ 49152       // A 16K + B 32K
#define NSTG 4
#define NITK (KTOT/64)       // 48

__global__ void __launch_bounds__(512, 1) k_lm_mma(float* __restrict__ out) {
    extern __shared__ __align__(128) char smem[];
    uint32_t sb = smem_u32(smem);
    int tid = threadIdx.x;
    int lane = tid & 31, wid = tid >> 5;
    int warp_m = wid & 3, warp_n = wid >> 2;
    int r0 = blockIdx.x * 128;      // M fastest: A stays L2-resident, B streams once
    int n0 = blockIdx.y * 256;

    const char* srcA = (const char*)g_Xs + ((size_t)r0 * KTOT) * 2;
    const char* srcB = (const char*)g_Ws + ((size_t)n0 * KTOT) * 2;

    int lrow = ((lane >> 3) & 1) * 8 + (lane & 7);
    int uadd = lane >> 4;
    int rA = warp_m * 32 + lrow;
    int rB = warp_n * 64 + lrow;
    int sA = rA & 7, sB = rB & 7;
    uint32_t aBase = sb + rA * 128;
    uint32_t bBase = sb + 16384 + rB * 128;

    float acc[2][8][4] = {};

    auto issue = [&](int kt, int stg) {
        uint32_t st = sb + stg * STAGE_SZ;
        #pragma unroll
        for (int j = 0; j < 2; j++) {           // A: 128 rows x 8 units
            int idx = tid + j*512;
            int row = idx >> 3, u = idx & 7;
            cp16(st + row*128 + ((u ^ (row & 7)) << 4),
                 srcA + ((size_t)row*KTOT + kt*64 + u*8) * 2);
        }
        #pragma unroll
        for (int j = 0; j < 4; j++) {           // B: 256 rows x 8 units
            int idx = tid + j*512;
            int row = idx >> 3, u = idx & 7;
            cp16(st + 16384 + row*128 + ((u ^ (row & 7)) << 4),
                 srcB + ((size_t)row*KTOT + kt*64 + u*8) * 2);
        }
        cp_commit();
    };

    issue(0, 0); issue(1, 1); issue(2, 2);

    for (int kt = 0; kt < NITK; kt++) {
        if (kt < NITK-2)      asm volatile("cp.async.wait_group 2;" ::: "memory");
        else if (kt < NITK-1) asm volatile("cp.async.wait_group 1;" ::: "memory");
        else                  asm volatile("cp.async.wait_group 0;" ::: "memory");
        __syncthreads();
        if (kt + 3 < NITK) issue(kt + 3, (kt + 3) & 3);

        uint32_t stA = aBase + (kt & 3) * STAGE_SZ;
        uint32_t stB = bBase + (kt & 3) * STAGE_SZ;
        #pragma unroll
        for (int kk = 0; kk < 4; kk++) {
            uint32_t af[2][4], bf[4][4];
            #pragma unroll
            for (int mt = 0; mt < 2; mt++)
                ldm_x4(af[mt], stA + mt*2048 + (((kk*2 + uadd) ^ sA) << 4));
            #pragma unroll
            for (int nt = 0; nt < 4; nt++)
                ldm_x4(bf[nt], stB + nt*2048 + (((kk*2 + uadd) ^ sB) << 4));
            #pragma unroll
            for (int mt = 0; mt < 2; mt++)
                #pragma unroll
                for (int nr = 0; nr < 8; nr++) {
                    uint32_t b2[2] = { bf[nr>>1][nr & 1], bf[nr>>1][(nr & 1) + 2] };
                    mma16816(acc[mt][nr], af[mt], b2);
                }
        }
        __syncthreads();
    }

    int orow = r0 + warp_m*32 + (lane >> 2);
    int ocol = n0 + warp_n*64 + (lane & 3)*2;
    #pragma unroll
    for (int mt = 0; mt < 2; mt++) {
        #pragma unroll
        for (int nr = 0; nr < 8; nr++) {
            int cc = ocol + (nr >> 1)*16 + (nr & 1)*8;
            size_t p0 = (size_t)(orow + mt*16)     * VV + cc;
            size_t p1 = (size_t)(orow + mt*16 + 8) * VV + cc;
            if (cc < VV)     { out[p0]   = acc[mt][nr][0]; out[p1]   = acc[mt][nr][2]; }
            if (cc + 1 < VV) { out[p0+1] = acc[mt][nr][1]; out[p1+1] = acc[mt][nr][3]; }
        }
    }
}

// ==================== launch ================================================
extern "C" void kernel_launch(void* const* d_in, const int* in_sizes, int n_in,
                              void* d_out, int out_size) {
    const int*   tokens   = (const int*)  d_in[0];
    const float* embW     = (const float*)d_in[1];
    const float* toW      = (const float*)d_in[2];
    const float* fwW      = (const float*)d_in[3];
    const float* speed    = (const float*)d_in[4];
    const float* dampen   = (const float*)d_in[5];
    const float* phase    = (const float*)d_in[6];
    const float* coupling = (const float*)d_in[7];
    const float* stepsc   = (const float*)d_in[8];
    const float* posf     = (const float*)d_in[9];
    const float* normsW   = (const float*)d_in[10];
    const float* onw      = (const float*)d_in[11];
    const float* lmW      = (const float*)d_in[12];
    float* out = (float*)d_out;

    cudaFuncSetAttribute(k_lm_mma,    cudaFuncAttributeMaxDynamicSharedMemorySize, NSTG*STAGE_SZ);
    cudaFuncSetAttribute(k_gemm1_mma, cudaFuncAttributeMaxDynamicSharedMemorySize, 3*G1_STG);
    cudaFuncSetAttribute(k_gemm2_mma, cudaFuncAttributeMaxDynamicSharedMemorySize, 3*G2_STG);

    k_prep_w2s<<<(DD*2*FF + 255)/256, 256>>>(speed, dampen, phase, coupling, fwW);
    k_convW1<<<2*FF, 256>>>(toW);
    k_tables<<<(SS*FF + 255)/256, 256>>>(posf);
    k_embed<<<MM, 256>>>(tokens, embW);
    k_convW<<<NPAD, 256>>>(lmW);

    for (int t = 0; t < TT; t++) {
        k_rmsconv<<<MM, 256>>>(normsW + (size_t)t*DD);
        k_gemm1_mma<<<MM/64, 256, 3*G1_STG>>>();
        k_convZ<<<MM/2, 128>>>();
        k_gemm2_mma<<<dim3(DD/128, MM/128), 256, 3*G2_STG>>>(stepsc, t);
    }

    k_rmsconv<<<MM, 256>>>(onw);
    k_lm_mma<<<dim3(MM/128, NPAD/256), 512, NSTG*STAGE_SZ>>>(out);
}

// round 9
// speedup vs baseline: 4.4099x; 1.9966x over previous
#include <cuda_runtime.h>
#include <cuda_fp16.h>
#include <math.h>
#include <math_constants.h>
#include <cstdint>

#define BB 2
#define SS 2048
#define DD 1024
#define FF 64
#define TT 28
#define VV 50257
#define MM (BB*SS)      // 4096
#define NPAD 50432      // 197 * 256
#define KD 1024         // single-pass fp16 K for D-sized GEMMs
#define K2 128          // gemm2 K (2F)

// ==================== scratch (device globals; no allocation) ===============
__device__ float g_x[(size_t)MM*DD];
__device__ float g_wc[(size_t)MM*2*FF];
__device__ float g_ct[(size_t)SS*FF];
__device__ float g_st[(size_t)SS*FF];
__device__ unsigned short g_Xh[(size_t)MM*KD];     // fp16 normed x
__device__ unsigned short g_Wh[(size_t)NPAD*KD];   // fp16 lm_head W
__device__ unsigned short g_W1h[(size_t)2*FF*KD];  // fp16 to_wave_W [128,1024]
__device__ unsigned short g_W2h[(size_t)DD*K2];    // fp16 W2^T      [1024,128]

// ==================== helpers ===============================================
__device__ __forceinline__ uint32_t smem_u32(const void* p) {
    uint32_t a;
    asm("{ .reg .u64 t; cvta.to.shared.u64 t, %1; cvt.u32.u64 %0, t; }" : "=r"(a) : "l"(p));
    return a;
}
__device__ __forceinline__ void cp16(uint32_t dst, const void* src) {
    asm volatile("cp.async.cg.shared.global [%0], [%1], 16;\n" :: "r"(dst), "l"(src) : "memory");
}
__device__ __forceinline__ void cp_commit() { asm volatile("cp.async.commit_group;\n" ::: "memory"); }

__device__ __forceinline__ void ldm_x4(uint32_t* r, uint32_t addr) {
    asm volatile("ldmatrix.sync.aligned.m8n8.x4.shared.b16 {%0,%1,%2,%3}, [%4];"
        : "=r"(r[0]), "=r"(r[1]), "=r"(r[2]), "=r"(r[3]) : "r"(addr));
}
__device__ __forceinline__ void mma16816(float* d, const uint32_t* a, const uint32_t* b) {
    asm volatile("mma.sync.aligned.m16n8k16.row.col.f32.f16.f16.f32 "
        "{%0,%1,%2,%3}, {%4,%5,%6,%7}, {%8,%9}, {%0,%1,%2,%3};"
        : "+f"(d[0]), "+f"(d[1]), "+f"(d[2]), "+f"(d[3])
        : "r"(a[0]), "r"(a[1]), "r"(a[2]), "r"(a[3]), "r"(b[0]), "r"(b[1]));
}

// ==================== one-time precompute ===================================
// W2h[d][j] = fp16( coef(j) * sum_g C[f,g]*fwW[d,g] ), j = 0..127
__global__ void k_prep_w2h(const float* __restrict__ speed,
                           const float* __restrict__ dampen,
                           const float* __restrict__ phase,
                           const float* __restrict__ coupling,
                           const float* __restrict__ fwW) {
    int idx = blockIdx.x * blockDim.x + threadIdx.x;
    if (idx >= DD*K2) return;
    int d = idx >> 7, j = idx & 127;
    int f = j & (FF-1);
    float dmp = dampen[f];
    float sp  = (dmp > 20.f) ? dmp : log1pf(expf(dmp));
    float m   = expf(-sp);
    float th  = speed[f] * CUDART_PI_F + phase[f];
    float c, s; sincosf(th, &s, &c);
    float coef = (j < FF) ? (m * c) : (-m * s);
    float acc = 0.f;
    #pragma unroll 8
    for (int g = 0; g < FF; g++) acc += coupling[f*FF+g] * fwW[d*FF+g];
    ((__half*)g_W2h)[idx] = __float2half_rn(coef * acc);
}

__global__ void k_convW1h(const float* __restrict__ toW) {
    int f = blockIdx.x;           // 0..127
    int tid = threadIdx.x;        // 256 * 4 elems
    float4 w = *(const float4*)(toW + (size_t)f*DD + tid*4);
    __half2* p = (__half2*)(g_W1h + (size_t)f*KD + tid*4);
    p[0] = __half2{__float2half_rn(w.x), __float2half_rn(w.y)};
    p[1] = __half2{__float2half_rn(w.z), __float2half_rn(w.w)};
}

__global__ void k_tables(const float* __restrict__ pf) {
    int idx = blockIdx.x * blockDim.x + threadIdx.x;
    if (idx >= SS*FF) return;
    int s = idx / FF, f = idx - s*FF;
    float th = (float)s * pf[f];
    float sn, cs; sincosf(th, &sn, &cs);
    g_ct[idx] = cs;
    g_st[idx] = sn;
}

__global__ void k_embed(const int* __restrict__ tokens,
                        const float* __restrict__ embW) {
    int r = blockIdx.x;
    int t = tokens[r];
    const float4* src = (const float4*)(embW + (size_t)t * DD);
    float4* dst = (float4*)(g_x + (size_t)r * DD);
    dst[threadIdx.x] = src[threadIdx.x];
}

__global__ void k_convWh(const float* __restrict__ lmW) {
    int v = blockIdx.x;           // 0 .. NPAD-1
    int tid = threadIdx.x;
    float4 w = make_float4(0.f, 0.f, 0.f, 0.f);
    if (v < VV) w = *(const float4*)(lmW + (size_t)v*DD + tid*4);
    __half2* p = (__half2*)(g_Wh + (size_t)v*KD + tid*4);
    p[0] = __half2{__float2half_rn(w.x), __float2half_rn(w.y)};
    p[1] = __half2{__float2half_rn(w.z), __float2half_rn(w.w)};
}

// ==================== fused rmsnorm + fp16 convert ==========================
__global__ void k_rmsconv(const float* __restrict__ nw) {
    int r = blockIdx.x;
    int tid = threadIdx.x;
    float4 v = ((const float4*)(g_x + (size_t)r*DD))[tid];
    float ss = v.x*v.x + v.y*v.y + v.z*v.z + v.w*v.w;
    #pragma unroll
    for (int o = 16; o; o >>= 1) ss += __shfl_xor_sync(0xffffffffu, ss, o);
    __shared__ float red[8];
    __shared__ float s_rinv;
    if ((tid & 31) == 0) red[tid >> 5] = ss;
    __syncthreads();
    if (tid < 8) {
        float t = red[tid];
        #pragma unroll
        for (int o = 4; o; o >>= 1) t += __shfl_xor_sync(0xffu, t, o);
        if (tid == 0) s_rinv = rsqrtf(t * (1.f/DD) + 1.1920929e-7f);
    }
    __syncthreads();
    float ri = s_rinv;
    float4 nwv = ((const float4*)nw)[tid];
    __half2* p = (__half2*)(g_Xh + (size_t)r*KD + tid*4);
    p[0] = __half2{__float2half_rn(v.x*ri*nwv.x), __float2half_rn(v.y*ri*nwv.y)};
    p[1] = __half2{__float2half_rn(v.z*ri*nwv.z), __float2half_rn(v.w*ri*nwv.w)};
}

// ==================== gemm1 (mma): wc = Xh @ W1h^T ==========================
// [4096,1024] x [128,1024]^T.  BM=32, BN=128, BK=64, 256 thr
// (8 warps: 2 warp_m x 4 warp_n, warp tile 16x32), 3-stage cp.async, 16 iters.
#define G1_STG 20480        // A 4K + B 16K
__global__ void __launch_bounds__(256, 1) k_gemm1_mma() {
    extern __shared__ __align__(128) char smem[];
    uint32_t sb = smem_u32(smem);
    int tid = threadIdx.x, lane = tid & 31, wid = tid >> 5;
    int warp_m = wid & 1, warp_n = wid >> 1;
    int r0 = blockIdx.x * 32;
    const char* srcA = (const char*)g_Xh + ((size_t)r0 * KD) * 2;
    const char* srcB = (const char*)g_W1h;
    int lrow = ((lane >> 3) & 1) * 8 + (lane & 7);
    int uadd = lane >> 4;
    int rA = warp_m*16 + lrow;
    int rB = warp_n*32 + lrow;
    int sA = rA & 7, sB = rB & 7;
    uint32_t aBase = sb + rA*128;
    uint32_t bBase = sb + 4096 + rB*128;
    float acc[4][4] = {};

    auto issue = [&](int kt, int stg) {
        uint32_t st = sb + stg*G1_STG;
        {                                        // A: 32 rows x 8 units = 256
            int row = tid >> 3, u = tid & 7;
            cp16(st + row*128 + ((u ^ (row & 7)) << 4),
                 srcA + ((size_t)row*KD + kt*64 + u*8) * 2);
        }
        #pragma unroll
        for (int j = 0; j < 4; j++) {            // B: 128 rows x 8 units
            int idx = tid + j*256; int row = idx >> 3, u = idx & 7;
            cp16(st + 4096 + row*128 + ((u ^ (row & 7)) << 4),
                 srcB + ((size_t)row*KD + kt*64 + u*8) * 2);
        }
        cp_commit();
    };
    issue(0, 0); issue(1, 1);
    const int NIT = KD/64;   // 16
    for (int kt = 0; kt < NIT; kt++) {
        if (kt < NIT-1) asm volatile("cp.async.wait_group 1;" ::: "memory");
        else            asm volatile("cp.async.wait_group 0;" ::: "memory");
        __syncthreads();
        if (kt + 2 < NIT) issue(kt + 2, (kt + 2) % 3);
        uint32_t stA = aBase + (kt % 3)*G1_STG;
        uint32_t stB = bBase + (kt % 3)*G1_STG;
        #pragma unroll
        for (int kk = 0; kk < 4; kk++) {
            uint32_t af[4], bf[2][4];
            ldm_x4(af, stA + (((kk*2 + uadd) ^ sA) << 4));
            #pragma unroll
            for (int nt = 0; nt < 2; nt++)
                ldm_x4(bf[nt], stB + nt*2048 + (((kk*2 + uadd) ^ sB) << 4));
            #pragma unroll
            for (int nr = 0; nr < 4; nr++) {
                uint32_t b2[2] = { bf[nr>>1][nr & 1], bf[nr>>1][(nr & 1) + 2] };
                mma16816(acc[nr], af, b2);
            }
        }
        __syncthreads();
    }
    int orow = r0 + warp_m*16 + (lane >> 2);
    int ocol = warp_n*32 + (lane & 3)*2;
    #pragma unroll
    for (int nr = 0; nr < 4; nr++) {
        int cc = ocol + (nr >> 1)*16 + (nr & 1)*8;
        size_t p0 = (size_t)orow*128 + cc;
        size_t p1 = (size_t)(orow + 8)*128 + cc;
        g_wc[p0] = acc[nr][0]; g_wc[p0+1] = acc[nr][1];
        g_wc[p1] = acc[nr][2]; g_wc[p1+1] = acc[nr][3];
    }
}

// ==================== gemm2 (mma): x += alpha * rot(wc) @ W2h^T =============
// Fused rotate+fp16-convert prologue; [4096,128] x [1024,128]^T.
// BM=128, BN=128, 256 thr (4 warp_m x 2 warp_n, warp 32x64), single-shot B.
#define G2_SMEM 65536       // A2 32K (2 kc x 16K) + B 32K
__global__ void __launch_bounds__(256, 1) k_gemm2_mma(const float* __restrict__ step_scale,
                                                      int t) {
    extern __shared__ __align__(128) char smem[];
    uint32_t sb = smem_u32(smem);
    int tid = threadIdx.x, lane = tid & 31, wid = tid >> 5;
    int warp_m = wid & 3, warp_n = wid >> 2;
    int r0 = blockIdx.y * 128;
    int n0 = blockIdx.x * 128;

    // B: [2 kc][128 rows][128B] swizzled, all via cp.async (overlaps rotate)
    #pragma unroll
    for (int j = 0; j < 8; j++) {
        int idx = tid + j*256;                 // 2048 cp16 total
        int kc = idx >> 10, rem = idx & 1023;
        int row = rem >> 3, u = rem & 7;
        cp16(sb + 32768 + kc*16384 + row*128 + ((u ^ (row & 7)) << 4),
             (const char*)g_W2h + ((size_t)(n0+row)*K2 + kc*64 + u*8) * 2);
    }
    cp_commit();

    // rotate+convert: thread -> (row = tid>>1, f-half = (tid&1)*32)
    {
        int row = tid >> 1, fh = (tid & 1) * 32;
        int r = r0 + row, s = r & (SS-1);
        const float* wr = g_wc + (size_t)r*128;
        const float* ctp = g_ct + (size_t)s*FF;
        const float* stp = g_st + (size_t)s*FF;
        #pragma unroll
        for (int q = 0; q < 8; q++) {
            int f = fh + q*4;
            float4 a  = *(const float4*)(wr + f);
            float4 b  = *(const float4*)(wr + 64 + f);
            float4 ct = *(const float4*)(ctp + f);
            float4 st = *(const float4*)(stp + f);
            __half2 zr0{__float2half_rn(a.x*ct.x - b.x*st.x), __float2half_rn(a.y*ct.y - b.y*st.y)};
            __half2 zr1{__float2half_rn(a.z*ct.z - b.z*st.z), __float2half_rn(a.w*ct.w - b.w*st.w)};
            __half2 zi0{__float2half_rn(a.x*st.x + b.x*ct.x), __float2half_rn(a.y*st.y + b.y*ct.y)};
            __half2 zi1{__float2half_rn(a.z*st.z + b.z*ct.z), __float2half_rn(a.w*st.w + b.w*ct.w)};
            uint32_t au = row*128 + ((((f >> 3) ^ (row & 7)) << 4) | ((f & 7) * 2));
            *(__half2*)(smem + au)             = zr0;   // k = f      (kc 0)
            *(__half2*)(smem + au + 4)         = zr1;
            *(__half2*)(smem + 16384 + au)     = zi0;   // k = 64+f   (kc 1)
            *(__half2*)(smem + 16384 + au + 4) = zi1;
        }
    }
    asm volatile("cp.async.wait_group 0;" ::: "memory");
    __syncthreads();

    int lrow = ((lane >> 3) & 1) * 8 + (lane & 7);
    int uadd = lane >> 4;
    int rA = warp_m*32 + lrow;
    int rB = warp_n*64 + lrow;
    int sA = rA & 7, sB = rB & 7;
    uint32_t aBase = sb + rA*128;
    uint32_t bBase = sb + 32768 + rB*128;
    float acc[2][8][4] = {};
    #pragma unroll
    for (int kt = 0; kt < 2; kt++) {
        uint32_t stA = aBase + kt*16384;
        uint32_t stB = bBase + kt*16384;
        #pragma unroll
        for (int kk = 0; kk < 4; kk++) {
            uint32_t af[2][4], bf[4][4];
            #pragma unroll
            for (int mt = 0; mt < 2; mt++)
                ldm_x4(af[mt], stA + mt*2048 + (((kk*2 + uadd) ^ sA) << 4));
            #pragma unroll
            for (int nt = 0; nt < 4; nt++)
                ldm_x4(bf[nt], stB + nt*2048 + (((kk*2 + uadd) ^ sB) << 4));
            #pragma unroll
            for (int mt = 0; mt < 2; mt++)
                #pragma unroll
                for (int nr = 0; nr < 8; nr++) {
                    uint32_t b2[2] = { bf[nr>>1][nr & 1], bf[nr>>1][(nr & 1) + 2] };
                    mma16816(acc[mt][nr], af[mt], b2);
                }
        }
    }
    float alpha = 0.1f * step_scale[t];
    int orow = r0 + warp_m*32 + (lane >> 2);
    int ocol = n0 + warp_n*64 + (lane & 3)*2;
    #pragma unroll
    for (int mt = 0; mt < 2; mt++) {
        #pragma unroll
        for (int nr = 0; nr < 8; nr++) {
            int cc = ocol + (nr >> 1)*16 + (nr & 1)*8;
            size_t p0 = (size_t)(orow + mt*16)     * DD + cc;
            size_t p1 = (size_t)(orow + mt*16 + 8) * DD + cc;
            g_x[p0]   += alpha*acc[mt][nr][0]; g_x[p0+1] += alpha*acc[mt][nr][1];
            g_x[p1]   += alpha*acc[mt][nr][2]; g_x[p1+1] += alpha*acc[mt][nr][3];
        }
    }
}

// ==================== fp16 lm_head GEMM (4-stage) ===========================
// out[4096, 50257] = Xh @ Wh^T over K=1024.
#define STAGE_SZ 49152       // A 16K + B 32K
#define NSTG 4
#define NITK (KD/64)         // 16

__global__ void __launch_bounds__(512, 1) k_lm_mma(float* __restrict__ out) {
    extern __shared__ __align__(128) char smem[];
    uint32_t sb = smem_u32(smem);
    int tid = threadIdx.x;
    int lane = tid & 31, wid = tid >> 5;
    int warp_m = wid & 3, warp_n = wid >> 2;
    int r0 = blockIdx.x * 128;      // M fastest: A stays L2-resident, B streams once
    int n0 = blockIdx.y * 256;

    const char* srcA = (const char*)g_Xh + ((size_t)r0 * KD) * 2;
    const char* srcB = (const char*)g_Wh + ((size_t)n0 * KD) * 2;

    int lrow = ((lane >> 3) & 1) * 8 + (lane & 7);
    int uadd = lane >> 4;
    int rA = warp_m * 32 + lrow;
    int rB = warp_n * 64 + lrow;
    int sA = rA & 7, sB = rB & 7;
    uint32_t aBase = sb + rA * 128;
    uint32_t bBase = sb + 16384 + rB * 128;

    float acc[2][8][4] = {};

    auto issue = [&](int kt, int stg) {
        uint32_t st = sb + stg * STAGE_SZ;
        #pragma unroll
        for (int j = 0; j < 2; j++) {           // A: 128 rows x 8 units
            int idx = tid + j*512;
            int row = idx >> 3, u = idx & 7;
            cp16(st + row*128 + ((u ^ (row & 7)) << 4),
                 srcA + ((size_t)row*KD + kt*64 + u*8) * 2);
        }
        #pragma unroll
        for (int j = 0; j < 4; j++) {           // B: 256 rows x 8 units
            int idx = tid + j*512;
            int row = idx >> 3, u = idx & 7;
            cp16(st + 16384 + row*128 + ((u ^ (row & 7)) << 4),
                 srcB + ((size_t)row*KD + kt*64 + u*8) * 2);
        }
        cp_commit();
    };

    issue(0, 0); issue(1, 1); issue(2, 2);

    for (int kt = 0; kt < NITK; kt++) {
        if (kt < NITK-2)      asm volatile("cp.async.wait_group 2;" ::: "memory");
        else if (kt < NITK-1) asm volatile("cp.async.wait_group 1;" ::: "memory");
        else                  asm volatile("cp.async.wait_group 0;" ::: "memory");
        __syncthreads();
        if (kt + 3 < NITK) issue(kt + 3, (kt + 3) & 3);

        uint32_t stA = aBase + (kt & 3) * STAGE_SZ;
        uint32_t stB = bBase + (kt & 3) * STAGE_SZ;
        #pragma unroll
        for (int kk = 0; kk < 4; kk++) {
            uint32_t af[2][4], bf[4][4];
            #pragma unroll
            for (int mt = 0; mt < 2; mt++)
                ldm_x4(af[mt], stA + mt*2048 + (((kk*2 + uadd) ^ sA) << 4));
            #pragma unroll
            for (int nt = 0; nt < 4; nt++)
                ldm_x4(bf[nt], stB + nt*2048 + (((kk*2 + uadd) ^ sB) << 4));
            #pragma unroll
            for (int mt = 0; mt < 2; mt++)
                #pragma unroll
                for (int nr = 0; nr < 8; nr++) {
                    uint32_t b2[2] = { bf[nr>>1][nr & 1], bf[nr>>1][(nr & 1) + 2] };
                    mma16816(acc[mt][nr], af[mt], b2);
                }
        }
        __syncthreads();
    }

    int orow = r0 + warp_m*32 + (lane >> 2);
    int ocol = n0 + warp_n*64 + (lane & 3)*2;
    #pragma unroll
    for (int mt = 0; mt < 2; mt++) {
        #pragma unroll
        for (int nr = 0; nr < 8; nr++) {
            int cc = ocol + (nr >> 1)*16 + (nr & 1)*8;
            size_t p0 = (size_t)(orow + mt*16)     * VV + cc;
            size_t p1 = (size_t)(orow + mt*16 + 8) * VV + cc;
            if (cc < VV)     { out[p0]   = acc[mt][nr][0]; out[p1]   = acc[mt][nr][2]; }
            if (cc + 1 < VV) { out[p0+1] = acc[mt][nr][1]; out[p1+1] = acc[mt][nr][3]; }
        }
    }
}

// ==================== launch ================================================
extern "C" void kernel_launch(void* const* d_in, const int* in_sizes, int n_in,
                              void* d_out, int out_size) {
    const int*   tokens   = (const int*)  d_in[0];
    const float* embW     = (const float*)d_in[1];
    const float* toW      = (const float*)d_in[2];
    const float* fwW      = (const float*)d_in[3];
    const float* speed    = (const float*)d_in[4];
    const float* dampen   = (const float*)d_in[5];
    const float* phase    = (const float*)d_in[6];
    const float* coupling = (const float*)d_in[7];
    const float* stepsc   = (const float*)d_in[8];
    const float* posf     = (const float*)d_in[9];
    const float* normsW   = (const float*)d_in[10];
    const float* onw      = (const float*)d_in[11];
    const float* lmW      = (const float*)d_in[12];
    float* out = (float*)d_out;

    cudaFuncSetAttribute(k_lm_mma,    cudaFuncAttributeMaxDynamicSharedMemorySize, NSTG*STAGE_SZ);
    cudaFuncSetAttribute(k_gemm1_mma, cudaFuncAttributeMaxDynamicSharedMemorySize, 3*G1_STG);
    cudaFuncSetAttribute(k_gemm2_mma, cudaFuncAttributeMaxDynamicSharedMemorySize, G2_SMEM);

    k_prep_w2h<<<(DD*K2 + 255)/256, 256>>>(speed, dampen, phase, coupling, fwW);
    k_convW1h<<<2*FF, 256>>>(toW);
    k_tables<<<(SS*FF + 255)/256, 256>>>(posf);
    k_embed<<<MM, 256>>>(tokens, embW);
    k_convWh<<<NPAD, 256>>>(lmW);

    for (int t = 0; t < TT; t++) {
        k_rmsconv<<<MM, 256>>>(normsW + (size_t)t*DD);
        k_gemm1_mma<<<MM/32, 256, 3*G1_STG>>>();
        k_gemm2_mma<<<dim3(DD/128, MM/128), 256, G2_SMEM>>>(stepsc, t);
    }

    k_rmsconv<<<MM, 256>>>(onw);
    k_lm_mma<<<dim3(MM/128, NPAD/256), 512, NSTG*STAGE_SZ>>>(out);
}

// round 10
// speedup vs baseline: 4.4814x; 1.0162x over previous
#include <cuda_runtime.h>
#include <cuda_fp16.h>
#include <math.h>
#include <math_constants.h>
#include <cstdint>

#define BB 2
#define SS 2048
#define DD 1024
#define FF 64
#define TT 28
#define VV 50257
#define MM (BB*SS)      // 4096
#define NPAD 50432      // 197 * 256
#define KD 1024         // fp16 K for D-sized GEMMs
#define K2 128          // gemm2 K (2F)

// ==================== scratch (device globals; no allocation) ===============
__device__ float g_x[(size_t)MM*DD];
__device__ float g_wc[(size_t)MM*2*FF];
__device__ float g_ct[(size_t)SS*FF];
__device__ float g_st[(size_t)SS*FF];
__device__ unsigned short g_Xh[(size_t)MM*KD];     // fp16 normed x (lm only)
__device__ unsigned short g_Wh[(size_t)NPAD*KD];   // fp16 lm_head W
__device__ unsigned short g_W1h[(size_t)2*FF*KD];  // fp16 to_wave_W [128,1024]
__device__ unsigned short g_W2h[(size_t)DD*K2];    // fp16 W2^T      [1024,128]

// ==================== helpers ===============================================
__device__ __forceinline__ uint32_t smem_u32(const void* p) {
    uint32_t a;
    asm("{ .reg .u64 t; cvta.to.shared.u64 t, %1; cvt.u32.u64 %0, t; }" : "=r"(a) : "l"(p));
    return a;
}
__device__ __forceinline__ void cp16(uint32_t dst, const void* src) {
    asm volatile("cp.async.cg.shared.global [%0], [%1], 16;\n" :: "r"(dst), "l"(src) : "memory");
}
__device__ __forceinline__ void cp_commit() { asm volatile("cp.async.commit_group;\n" ::: "memory"); }

__device__ __forceinline__ void ldm_x4(uint32_t* r, uint32_t addr) {
    asm volatile("ldmatrix.sync.aligned.m8n8.x4.shared.b16 {%0,%1,%2,%3}, [%4];"
        : "=r"(r[0]), "=r"(r[1]), "=r"(r[2]), "=r"(r[3]) : "r"(addr));
}
__device__ __forceinline__ void mma16816(float* d, const uint32_t* a, const uint32_t* b) {
    asm volatile("mma.sync.aligned.m16n8k16.row.col.f32.f16.f16.f32 "
        "{%0,%1,%2,%3}, {%4,%5,%6,%7}, {%8,%9}, {%0,%1,%2,%3};"
        : "+f"(d[0]), "+f"(d[1]), "+f"(d[2]), "+f"(d[3])
        : "r"(a[0]), "r"(a[1]), "r"(a[2]), "r"(a[3]), "r"(b[0]), "r"(b[1]));
}

// ==================== one-time precompute ===================================
__global__ void k_prep_w2h(const float* __restrict__ speed,
                           const float* __restrict__ dampen,
                           const float* __restrict__ phase,
                           const float* __restrict__ coupling,
                           const float* __restrict__ fwW) {
    int idx = blockIdx.x * blockDim.x + threadIdx.x;
    if (idx >= DD*K2) return;
    int d = idx >> 7, j = idx & 127;
    int f = j & (FF-1);
    float dmp = dampen[f];
    float sp  = (dmp > 20.f) ? dmp : log1pf(expf(dmp));
    float m   = expf(-sp);
    float th  = speed[f] * CUDART_PI_F + phase[f];
    float c, s; sincosf(th, &s, &c);
    float coef = (j < FF) ? (m * c) : (-m * s);
    float acc = 0.f;
    #pragma unroll 8
    for (int g = 0; g < FF; g++) acc += coupling[f*FF+g] * fwW[d*FF+g];
    ((__half*)g_W2h)[idx] = __float2half_rn(coef * acc);
}

__global__ void k_convW1h(const float* __restrict__ toW) {
    int f = blockIdx.x;
    int tid = threadIdx.x;
    float4 w = *(const float4*)(toW + (size_t)f*DD + tid*4);
    __half2* p = (__half2*)(g_W1h + (size_t)f*KD + tid*4);
    p[0] = __half2{__float2half_rn(w.x), __float2half_rn(w.y)};
    p[1] = __half2{__float2half_rn(w.z), __float2half_rn(w.w)};
}

__global__ void k_tables(const float* __restrict__ pf) {
    int idx = blockIdx.x * blockDim.x + threadIdx.x;
    if (idx >= SS*FF) return;
    int s = idx / FF, f = idx - s*FF;
    float th = (float)s * pf[f];
    float sn, cs; sincosf(th, &sn, &cs);
    g_ct[idx] = cs;
    g_st[idx] = sn;
}

__global__ void k_embed(const int* __restrict__ tokens,
                        const float* __restrict__ embW) {
    int r = blockIdx.x;
    int t = tokens[r];
    const float4* src = (const float4*)(embW + (size_t)t * DD);
    float4* dst = (float4*)(g_x + (size_t)r * DD);
    dst[threadIdx.x] = src[threadIdx.x];
}

__global__ void k_convWh(const float* __restrict__ lmW) {
    int v = blockIdx.x;
    int tid = threadIdx.x;
    float4 w = make_float4(0.f, 0.f, 0.f, 0.f);
    if (v < VV) w = *(const float4*)(lmW + (size_t)v*DD + tid*4);
    __half2* p = (__half2*)(g_Wh + (size_t)v*KD + tid*4);
    p[0] = __half2{__float2half_rn(w.x), __float2half_rn(w.y)};
    p[1] = __half2{__float2half_rn(w.z), __float2half_rn(w.w)};
}

// ==================== rmsnorm + fp16 convert (final, for lm) ================
__global__ void k_rmsconv(const float* __restrict__ nw) {
    int r = blockIdx.x;
    int tid = threadIdx.x;
    float4 v = ((const float4*)(g_x + (size_t)r*DD))[tid];
    float ss = v.x*v.x + v.y*v.y + v.z*v.z + v.w*v.w;
    #pragma unroll
    for (int o = 16; o; o >>= 1) ss += __shfl_xor_sync(0xffffffffu, ss, o);
    __shared__ float red[8];
    __shared__ float s_rinv;
    if ((tid & 31) == 0) red[tid >> 5] = ss;
    __syncthreads();
    if (tid < 8) {
        float t = red[tid];
        #pragma unroll
        for (int o = 4; o; o >>= 1) t += __shfl_xor_sync(0xffu, t, o);
        if (tid == 0) s_rinv = rsqrtf(t * (1.f/DD) + 1.1920929e-7f);
    }
    __syncthreads();
    float ri = s_rinv;
    float4 nwv = ((const float4*)nw)[tid];
    __half2* p = (__half2*)(g_Xh + (size_t)r*KD + tid*4);
    p[0] = __half2{__float2half_rn(v.x*ri*nwv.x), __float2half_rn(v.y*ri*nwv.y)};
    p[1] = __half2{__float2half_rn(v.z*ri*nwv.z), __float2half_rn(v.w*ri*nwv.w)};
}

// ==================== fused rms + gemm1: wc = rms(x)*nw @ W1h^T =============
// [4096,1024] x [128,1024]^T.  BM=32, BN=128.  256 thr.
// Phase A: 2-pass rms over g_x rows; converts WHOLE fp16 A tile (32x1024,
// 64KB) into resident smem (16 k-tiles, swizzled). Only B is cp.async-staged.
#define G1_A_BYTES 65536               // 16 ktiles * 32 rows * 128B
#define G1_B_STG   16384               // 128 rows * 128B
#define G1_SMEM    (G1_A_BYTES + 3*G1_B_STG)   // 114688
__global__ void __launch_bounds__(256, 1) k_gemm1_mma(const float* __restrict__ nw) {
    extern __shared__ __align__(128) char smem[];
    uint32_t sb = smem_u32(smem);
    uint32_t sbB = sb + G1_A_BYTES;
    __shared__ float s_sum[32];
    __shared__ float s_rinv[32];
    int tid = threadIdx.x, lane = tid & 31, wid = tid >> 5;
    int warp_m = wid & 1, warp_n = wid >> 1;
    int r0 = blockIdx.x * 32;
    const char* srcB = (const char*)g_W1h;

    // kick off B stages 0,1 first (overlap with rms phase)
    auto issueB = [&](int kt, int stg) {
        uint32_t st = sbB + stg*G1_B_STG;
        #pragma unroll
        for (int j = 0; j < 4; j++) {
            int idx = tid + j*256; int row = idx >> 3, u = idx & 7;
            cp16(st + row*128 + ((u ^ (row & 7)) << 4),
                 srcB + ((size_t)row*KD + kt*64 + u*8) * 2);
        }
        cp_commit();
    };
    issueB(0, 0); issueB(1, 1);

    // ---- phase A: rms + convert A into resident smem ----------------------
    int arow = tid >> 3, au = tid & 7;            // 8 threads per row
    const float* xrow = g_x + (size_t)(r0 + arow)*DD;
    float sum = 0.f;
    #pragma unroll
    for (int kt = 0; kt < 16; kt++) {
        float4 a = *(const float4*)(xrow + kt*64 + au*8);
        float4 b = *(const float4*)(xrow + kt*64 + au*8 + 4);
        sum += a.x*a.x + a.y*a.y + a.z*a.z + a.w*a.w
             + b.x*b.x + b.y*b.y + b.z*b.z + b.w*b.w;
    }
    #pragma unroll
    for (int o = 1; o < 8; o <<= 1) sum += __shfl_xor_sync(0xffffffffu, sum, o);
    if (au == 0) s_sum[arow] = sum;
    __syncthreads();
    if (tid < 32) s_rinv[tid] = rsqrtf(s_sum[tid] * (1.f/DD) + 1.1920929e-7f);
    __syncthreads();
    float ri = s_rinv[arow];
    uint32_t aDst = sb + arow*128 + ((au ^ (arow & 7)) << 4);
    #pragma unroll
    for (int kt = 0; kt < 16; kt++) {
        float4 a = *(const float4*)(xrow + kt*64 + au*8);
        float4 b = *(const float4*)(xrow + kt*64 + au*8 + 4);
        float4 n0 = __ldg((const float4*)(nw + kt*64 + au*8));
        float4 n1 = __ldg((const float4*)(nw + kt*64 + au*8 + 4));
        __half2 h0{__float2half_rn(a.x*ri*n0.x), __float2half_rn(a.y*ri*n0.y)};
        __half2 h1{__float2half_rn(a.z*ri*n0.z), __float2half_rn(a.w*ri*n0.w)};
        __half2 h2{__float2half_rn(b.x*ri*n1.x), __float2half_rn(b.y*ri*n1.y)};
        __half2 h3{__float2half_rn(b.z*ri*n1.z), __float2half_rn(b.w*ri*n1.w)};
        uint4 pk;
        pk.x = *(uint32_t*)&h0; pk.y = *(uint32_t*)&h1;
        pk.z = *(uint32_t*)&h2; pk.w = *(uint32_t*)&h3;
        *(uint4*)(smem + (aDst - sb) + kt*4096) = pk;
    }
    __syncthreads();

    // ---- main loop: B staged, A resident ----------------------------------
    int lrow = ((lane >> 3) & 1) * 8 + (lane & 7);
    int uadd = lane >> 4;
    int rA = warp_m*16 + lrow;
    int rB = warp_n*32 + lrow;
    int sA = rA & 7, sB = rB & 7;
    uint32_t aBase = sb + rA*128;
    uint32_t bBase = sbB + rB*128;
    float acc[4][4] = {};
    const int NIT = KD/64;   // 16
    for (int kt = 0; kt < NIT; kt++) {
        if (kt < NIT-1) asm volatile("cp.async.wait_group 1;" ::: "memory");
        else            asm volatile("cp.async.wait_group 0;" ::: "memory");
        __syncthreads();
        if (kt + 2 < NIT) issueB(kt + 2, (kt + 2) % 3);
        uint32_t stA = aBase + kt*4096;
        uint32_t stB = bBase + (kt % 3)*G1_B_STG;
        #pragma unroll
        for (int kk = 0; kk < 4; kk++) {
            uint32_t af[4], bf[2][4];
            ldm_x4(af, stA + (((kk*2 + uadd) ^ sA) << 4));
            #pragma unroll
            for (int nt = 0; nt < 2; nt++)
                ldm_x4(bf[nt], stB + nt*2048 + (((kk*2 + uadd) ^ sB) << 4));
            #pragma unroll
            for (int nr = 0; nr < 4; nr++) {
                uint32_t b2[2] = { bf[nr>>1][nr & 1], bf[nr>>1][(nr & 1) + 2] };
                mma16816(acc[nr], af, b2);
            }
        }
        __syncthreads();
    }
    int orow = r0 + warp_m*16 + (lane >> 2);
    int ocol = warp_n*32 + (lane & 3)*2;
    #pragma unroll
    for (int nr = 0; nr < 4; nr++) {
        int cc = ocol + (nr >> 1)*16 + (nr & 1)*8;
        size_t p0 = (size_t)orow*128 + cc;
        size_t p1 = (size_t)(orow + 8)*128 + cc;
        g_wc[p0] = acc[nr][0]; g_wc[p0+1] = acc[nr][1];
        g_wc[p1] = acc[nr][2]; g_wc[p1+1] = acc[nr][3];
    }
}

// ==================== gemm2 (mma): x += alpha * rot(wc) @ W2h^T =============
#define G2_SMEM 65536       // A 32K (2 kc x 16K) + B 32K
__global__ void __launch_bounds__(256, 1) k_gemm2_mma(const float* __restrict__ step_scale,
                                                      int t) {
    extern __shared__ __align__(128) char smem[];
    uint32_t sb = smem_u32(smem);
    int tid = threadIdx.x, lane = tid & 31, wid = tid >> 5;
    int warp_m = wid & 3, warp_n = wid >> 2;
    int r0 = blockIdx.y * 128;
    int n0 = blockIdx.x * 128;

    #pragma unroll
    for (int j = 0; j < 8; j++) {
        int idx = tid + j*256;
        int kc = idx >> 10, rem = idx & 1023;
        int row = rem >> 3, u = rem & 7;
        cp16(sb + 32768 + kc*16384 + row*128 + ((u ^ (row & 7)) << 4),
             (const char*)g_W2h + ((size_t)(n0+row)*K2 + kc*64 + u*8) * 2);
    }
    cp_commit();

    {
        int row = tid >> 1, fh = (tid & 1) * 32;
        int r = r0 + row, s = r & (SS-1);
        const float* wr = g_wc + (size_t)r*128;
        const float* ctp = g_ct + (size_t)s*FF;
        const float* stp = g_st + (size_t)s*FF;
        #pragma unroll
        for (int q = 0; q < 8; q++) {
            int f = fh + q*4;
            float4 a  = *(const float4*)(wr + f);
            float4 b  = *(const float4*)(wr + 64 + f);
            float4 ct = *(const float4*)(ctp + f);
            float4 st = *(const float4*)(stp + f);
            __half2 zr0{__float2half_rn(a.x*ct.x - b.x*st.x), __float2half_rn(a.y*ct.y - b.y*st.y)};
            __half2 zr1{__float2half_rn(a.z*ct.z - b.z*st.z), __float2half_rn(a.w*ct.w - b.w*st.w)};
            __half2 zi0{__float2half_rn(a.x*st.x + b.x*ct.x), __float2half_rn(a.y*st.y + b.y*ct.y)};
            __half2 zi1{__float2half_rn(a.z*st.z + b.z*ct.z), __float2half_rn(a.w*st.w + b.w*ct.w)};
            uint32_t au = row*128 + ((((f >> 3) ^ (row & 7)) << 4) | ((f & 7) * 2));
            *(__half2*)(smem + au)             = zr0;
            *(__half2*)(smem + au + 4)         = zr1;
            *(__half2*)(smem + 16384 + au)     = zi0;
            *(__half2*)(smem + 16384 + au + 4) = zi1;
        }
    }
    asm volatile("cp.async.wait_group 0;" ::: "memory");
    __syncthreads();

    int lrow = ((lane >> 3) & 1) * 8 + (lane & 7);
    int uadd = lane >> 4;
    int rA = warp_m*32 + lrow;
    int rB = warp_n*64 + lrow;
    int sA = rA & 7, sB = rB & 7;
    uint32_t aBase = sb + rA*128;
    uint32_t bBase = sb + 32768 + rB*128;
    float acc[2][8][4] = {};
    #pragma unroll
    for (int kt = 0; kt < 2; kt++) {
        uint32_t stA = aBase + kt*16384;
        uint32_t stB = bBase + kt*16384;
        #pragma unroll
        for (int kk = 0; kk < 4; kk++) {
            uint32_t af[2][4], bf[4][4];
            #pragma unroll
            for (int mt = 0; mt < 2; mt++)
                ldm_x4(af[mt], stA + mt*2048 + (((kk*2 + uadd) ^ sA) << 4));
            #pragma unroll
            for (int nt = 0; nt < 4; nt++)
                ldm_x4(bf[nt], stB + nt*2048 + (((kk*2 + uadd) ^ sB) << 4));
            #pragma unroll
            for (int mt = 0; mt < 2; mt++)
                #pragma unroll
                for (int nr = 0; nr < 8; nr++) {
                    uint32_t b2[2] = { bf[nr>>1][nr & 1], bf[nr>>1][(nr & 1) + 2] };
                    mma16816(acc[mt][nr], af[mt], b2);
                }
        }
    }
    float alpha = 0.1f * step_scale[t];
    int orow = r0 + warp_m*32 + (lane >> 2);
    int ocol = n0 + warp_n*64 + (lane & 3)*2;
    #pragma unroll
    for (int mt = 0; mt < 2; mt++) {
        #pragma unroll
        for (int nr = 0; nr < 8; nr++) {
            int cc = ocol + (nr >> 1)*16 + (nr & 1)*8;
            size_t p0 = (size_t)(orow + mt*16)     * DD + cc;
            size_t p1 = (size_t)(orow + mt*16 + 8) * DD + cc;
            g_x[p0]   += alpha*acc[mt][nr][0]; g_x[p0+1] += alpha*acc[mt][nr][1];
            g_x[p1]   += alpha*acc[mt][nr][2]; g_x[p1+1] += alpha*acc[mt][nr][3];
        }
    }
}

// ==================== fp16 lm_head GEMM (4-stage) ===========================
#define STAGE_SZ 49152       // A 16K + B 32K
#define NSTG 4
#define NITK (KD/64)         // 16

__global__ void __launch_bounds__(512, 1) k_lm_mma(float* __restrict__ out) {
    extern __shared__ __align__(128) char smem[];
    uint32_t sb = smem_u32(smem);
    int tid = threadIdx.x;
    int lane = tid & 31, wid = tid >> 5;
    int warp_m = wid & 3, warp_n = wid >> 2;
    int r0 = blockIdx.x * 128;      // M fastest: A stays L2-resident, B streams once
    int n0 = blockIdx.y * 256;

    const char* srcA = (const char*)g_Xh + ((size_t)r0 * KD) * 2;
    const char* srcB = (const char*)g_Wh + ((size_t)n0 * KD) * 2;

    int lrow = ((lane >> 3) & 1) * 8 + (lane & 7);
    int uadd = lane >> 4;
    int rA = warp_m * 32 + lrow;
    int rB = warp_n * 64 + lrow;
    int sA = rA & 7, sB = rB & 7;
    uint32_t aBase = sb + rA * 128;
    uint32_t bBase = sb + 16384 + rB * 128;

    float acc[2][8][4] = {};

    auto issue = [&](int kt, int stg) {
        uint32_t st = sb + stg * STAGE_SZ;
        #pragma unroll
        for (int j = 0; j < 2; j++) {
            int idx = tid + j*512;
            int row = idx >> 3, u = idx & 7;
            cp16(st + row*128 + ((u ^ (row & 7)) << 4),
                 srcA + ((size_t)row*KD + kt*64 + u*8) * 2);
        }
        #pragma unroll
        for (int j = 0; j < 4; j++) {
            int idx = tid + j*512;
            int row = idx >> 3, u = idx & 7;
            cp16(st + 16384 + row*128 + ((u ^ (row & 7)) << 4),
                 srcB + ((size_t)row*KD + kt*64 + u*8) * 2);
        }
        cp_commit();
    };

    issue(0, 0); issue(1, 1); issue(2, 2);

    for (int kt = 0; kt < NITK; kt++) {
        if (kt < NITK-2)      asm volatile("cp.async.wait_group 2;" ::: "memory");
        else if (kt < NITK-1) asm volatile("cp.async.wait_group 1;" ::: "memory");
        else                  asm volatile("cp.async.wait_group 0;" ::: "memory");
        __syncthreads();
        if (kt + 3 < NITK) issue(kt + 3, (kt + 3) & 3);

        uint32_t stA = aBase + (kt & 3) * STAGE_SZ;
        uint32_t stB = bBase + (kt & 3) * STAGE_SZ;
        #pragma unroll
        for (int kk = 0; kk < 4; kk++) {
            uint32_t af[2][4], bf[4][4];
            #pragma unroll
            for (int mt = 0; mt < 2; mt++)
                ldm_x4(af[mt], stA + mt*2048 + (((kk*2 + uadd) ^ sA) << 4));
            #pragma unroll
            for (int nt = 0; nt < 4; nt++)
                ldm_x4(bf[nt], stB + nt*2048 + (((kk*2 + uadd) ^ sB) << 4));
            #pragma unroll
            for (int mt = 0; mt < 2; mt++)
                #pragma unroll
                for (int nr = 0; nr < 8; nr++) {
                    uint32_t b2[2] = { bf[nr>>1][nr & 1], bf[nr>>1][(nr & 1) + 2] };
                    mma16816(acc[mt][nr], af[mt], b2);
                }
        }
        __syncthreads();
    }

    int orow = r0 + warp_m*32 + (lane >> 2);
    int ocol = n0 + warp_n*64 + (lane & 3)*2;
    #pragma unroll
    for (int mt = 0; mt < 2; mt++) {
        #pragma unroll
        for (int nr = 0; nr < 8; nr++) {
            int cc = ocol + (nr >> 1)*16 + (nr & 1)*8;
            size_t p0 = (size_t)(orow + mt*16)     * VV + cc;
            size_t p1 = (size_t)(orow + mt*16 + 8) * VV + cc;
            if (cc < VV)     { out[p0]   = acc[mt][nr][0]; out[p1]   = acc[mt][nr][2]; }
            if (cc + 1 < VV) { out[p0+1] = acc[mt][nr][1]; out[p1+1] = acc[mt][nr][3]; }
        }
    }
}

// ==================== launch ================================================
extern "C" void kernel_launch(void* const* d_in, const int* in_sizes, int n_in,
                              void* d_out, int out_size) {
    const int*   tokens   = (const int*)  d_in[0];
    const float* embW     = (const float*)d_in[1];
    const float* toW      = (const float*)d_in[2];
    const float* fwW      = (const float*)d_in[3];
    const float* speed    = (const float*)d_in[4];
    const float* dampen   = (const float*)d_in[5];
    const float* phase    = (const float*)d_in[6];
    const float* coupling = (const float*)d_in[7];
    const float* stepsc   = (const float*)d_in[8];
    const float* posf     = (const float*)d_in[9];
    const float* normsW   = (const float*)d_in[10];
    const float* onw      = (const float*)d_in[11];
    const float* lmW      = (const float*)d_in[12];
    float* out = (float*)d_out;

    cudaFuncSetAttribute(k_lm_mma,    cudaFuncAttributeMaxDynamicSharedMemorySize, NSTG*STAGE_SZ);
    cudaFuncSetAttribute(k_gemm1_mma, cudaFuncAttributeMaxDynamicSharedMemorySize, G1_SMEM);
    cudaFuncSetAttribute(k_gemm2_mma, cudaFuncAttributeMaxDynamicSharedMemorySize, G2_SMEM);

    k_prep_w2h<<<(DD*K2 + 255)/256, 256>>>(speed, dampen, phase, coupling, fwW);
    k_convW1h<<<2*FF, 256>>>(toW);
    k_tables<<<(SS*FF + 255)/256, 256>>>(posf);
    k_embed<<<MM, 256>>>(tokens, embW);
    k_convWh<<<NPAD, 256>>>(lmW);

    for (int t = 0; t < TT; t++) {
        k_gemm1_mma<<<MM/32, 256, G1_SMEM>>>(normsW + (size_t)t*DD);
        k_gemm2_mma<<<dim3(DD/128, MM/128), 256, G2_SMEM>>>(stepsc, t);
    }

    k_rmsconv<<<MM, 256>>>(onw);
    k_lm_mma<<<dim3(MM/128, NPAD/256), 512, NSTG*STAGE_SZ>>>(out);
}

// round 11
// speedup vs baseline: 5.6105x; 1.2520x over previous
#include <cuda_runtime.h>
#include <cuda_fp16.h>
#include <math.h>
#include <math_constants.h>
#include <cstdint>

#define BB 2
#define SS 2048
#define DD 1024
#define FF 64
#define TT 28
#define VV 50257
#define MM (BB*SS)      // 4096
#define NPAD 50432      // 197 * 256
#define KD 1024
#define K2 128
#define RPC 32          // rows per CTA in the persistent step kernel
#define XP 1032         // padded sx row pitch (floats) — bank rotation

// ==================== scratch (device globals; no allocation) ===============
__device__ float g_x[(size_t)MM*DD];
__device__ float g_ct[(size_t)SS*FF];
__device__ float g_st[(size_t)SS*FF];
__device__ unsigned short g_Xh[(size_t)MM*KD];     // fp16 normed x (lm A)
__device__ unsigned short g_Wh[(size_t)NPAD*KD];   // fp16 lm_head W
__device__ unsigned short g_W1h[(size_t)2*FF*KD];  // fp16 to_wave_W [128,1024]
__device__ unsigned short g_W2h[(size_t)DD*K2];    // fp16 W2^T      [1024,128]

// ==================== helpers ===============================================
__device__ __forceinline__ uint32_t smem_u32(const void* p) {
    uint32_t a;
    asm("{ .reg .u64 t; cvta.to.shared.u64 t, %1; cvt.u32.u64 %0, t; }" : "=r"(a) : "l"(p));
    return a;
}
__device__ __forceinline__ void cp16(uint32_t dst, const void* src) {
    asm volatile("cp.async.cg.shared.global [%0], [%1], 16;\n" :: "r"(dst), "l"(src) : "memory");
}
__device__ __forceinline__ void cp_commit() { asm volatile("cp.async.commit_group;\n" ::: "memory"); }

__device__ __forceinline__ void ldm_x4(uint32_t* r, uint32_t addr) {
    asm volatile("ldmatrix.sync.aligned.m8n8.x4.shared.b16 {%0,%1,%2,%3}, [%4];"
        : "=r"(r[0]), "=r"(r[1]), "=r"(r[2]), "=r"(r[3]) : "r"(addr));
}
__device__ __forceinline__ void mma16816(float* d, const uint32_t* a, const uint32_t* b) {
    asm volatile("mma.sync.aligned.m16n8k16.row.col.f32.f16.f16.f32 "
        "{%0,%1,%2,%3}, {%4,%5,%6,%7}, {%8,%9}, {%0,%1,%2,%3};"
        : "+f"(d[0]), "+f"(d[1]), "+f"(d[2]), "+f"(d[3])
        : "r"(a[0]), "r"(a[1]), "r"(a[2]), "r"(a[3]), "r"(b[0]), "r"(b[1]));
}

// ==================== one-time precompute ===================================
__global__ void k_prep_w2h(const float* __restrict__ speed,
                           const float* __restrict__ dampen,
                           const float* __restrict__ phase,
                           const float* __restrict__ coupling,
                           const float* __restrict__ fwW) {
    int idx = blockIdx.x * blockDim.x + threadIdx.x;
    if (idx >= DD*K2) return;
    int d = idx >> 7, j = idx & 127;
    int f = j & (FF-1);
    float dmp = dampen[f];
    float sp  = (dmp > 20.f) ? dmp : log1pf(expf(dmp));
    float m   = expf(-sp);
    float th  = speed[f] * CUDART_PI_F + phase[f];
    float c, s; sincosf(th, &s, &c);
    float coef = (j < FF) ? (m * c) : (-m * s);
    float acc = 0.f;
    #pragma unroll 8
    for (int g = 0; g < FF; g++) acc += coupling[f*FF+g] * fwW[d*FF+g];
    ((__half*)g_W2h)[idx] = __float2half_rn(coef * acc);
}

__global__ void k_convW1h(const float* __restrict__ toW) {
    int f = blockIdx.x;
    int tid = threadIdx.x;
    float4 w = *(const float4*)(toW + (size_t)f*DD + tid*4);
    __half2* p = (__half2*)(g_W1h + (size_t)f*KD + tid*4);
    p[0] = __half2{__float2half_rn(w.x), __float2half_rn(w.y)};
    p[1] = __half2{__float2half_rn(w.z), __float2half_rn(w.w)};
}

__global__ void k_tables(const float* __restrict__ pf) {
    int idx = blockIdx.x * blockDim.x + threadIdx.x;
    if (idx >= SS*FF) return;
    int s = idx / FF, f = idx - s*FF;
    float th = (float)s * pf[f];
    float sn, cs; sincosf(th, &sn, &cs);
    g_ct[idx] = cs;
    g_st[idx] = sn;
}

__global__ void k_embed(const int* __restrict__ tokens,
                        const float* __restrict__ embW) {
    int r = blockIdx.x;
    int t = tokens[r];
    const float4* src = (const float4*)(embW + (size_t)t * DD);
    float4* dst = (float4*)(g_x + (size_t)r * DD);
    dst[threadIdx.x] = src[threadIdx.x];
}

__global__ void k_convWh(const float* __restrict__ lmW) {
    int v = blockIdx.x;
    int tid = threadIdx.x;
    float4 w = make_float4(0.f, 0.f, 0.f, 0.f);
    if (v < VV) w = *(const float4*)(lmW + (size_t)v*DD + tid*4);
    __half2* p = (__half2*)(g_Wh + (size_t)v*KD + tid*4);
    p[0] = __half2{__float2half_rn(w.x), __float2half_rn(w.y)};
    p[1] = __half2{__float2half_rn(w.z), __float2half_rn(w.w)};
}

// ==================== persistent step kernel ================================
// 128 CTAs x 256 threads; each CTA owns 32 rows of x resident in smem for all
// 28 steps. Per step: rms -> gemm1 (A converted per-ktile, B=W1h streamed) ->
// wc->rotate->zh -> gemm2 (A=zh resident, B=W2h streamed) accumulating into
// smem x. Final: rms with out_norm -> g_Xh.
//
// smem layout (bytes):
#define O_SX    0                         // 32 x 1032 fp32 = 132096
#define O_TC    132096                    // ct 32x64 fp32  = 8192
#define O_TS    140288                    // st 32x64 fp32  = 8192
#define O_NW    148480                    // nw 1024 fp32   = 4096
#define O_RV    152576                    // rinv 32 fp32   = 128
#define O_ZH    152704                    // z fp16 2 planes x 32x128B = 8192
#define O_AH    160896                    // A fp16 ktile x2 = 8192
#define O_BST   169088                    // B staging 3 x 16384 = 49152
#define STEP_SMEM 218240
#define WCP 132                           // wc staging pitch (floats), in BST

__global__ void __launch_bounds__(256, 1)
k_step(const float* __restrict__ normsW,
       const float* __restrict__ stepsc,
       const float* __restrict__ onw) {
    extern __shared__ __align__(128) char smem[];
    uint32_t sb = smem_u32(smem);
    float* SX  = (float*)smem;
    float* TC  = (float*)(smem + O_TC);
    float* TS  = (float*)(smem + O_TS);
    float* NW  = (float*)(smem + O_NW);
    float* RV  = (float*)(smem + O_RV);
    float* WC  = (float*)(smem + O_BST);   // wc staging reuses B region

    int tid = threadIdx.x, lane = tid & 31, wid = tid >> 5;
    int r0 = blockIdx.x * RPC;
    int arow = tid >> 3, au = tid & 7;     // 8 threads per owned row

    // ---- init: x rows + rotation tables into smem -------------------------
    for (int i = tid; i < RPC*256; i += 256) {       // 8192 float4
        int row = i >> 8, c4 = i & 255;
        *(float4*)(SX + (size_t)row*XP + c4*4) =
            ((const float4*)(g_x + (size_t)(r0+row)*DD))[c4];
    }
    for (int i = tid; i < RPC*FF; i += 256) {
        int row = i >> 6, f = i & 63;
        int s = (r0 + row) & (SS-1);
        TC[i] = g_ct[(size_t)s*FF + f];
        TS[i] = g_st[(size_t)s*FF + f];
    }
    __syncthreads();

    // gemm1 warp layout: 2 warp_m x 4 warp_n, warp tile 16x32
    int warp_m1 = wid & 1, warp_n1 = wid >> 1;
    // gemm2 warp layout: 2 warp_m x 4 warp_n, warp tile 16x16 (per 64-col chunk)
    int lrow = ((lane >> 3) & 1) * 8 + (lane & 7);
    int uadd = lane >> 4;
    int rA1 = warp_m1*16 + lrow, sA1 = rA1 & 7;
    int rB1 = warp_n1*32 + lrow, sB1 = rB1 & 7;
    int rA2 = warp_m1*16 + lrow, sA2 = rA2 & 7;       // same 16-row coverage
    int rB2 = warp_n1*16 + lrow, sB2 = rB2 & 7;

    const float* xr = SX + (size_t)arow*XP;

    auto issueB1 = [&](int kt, int stg) {
        uint32_t st = sb + O_BST + stg*16384;
        #pragma unroll
        for (int j = 0; j < 4; j++) {                // 128 rows x 8 units
            int idx = tid + j*256; int row = idx >> 3, u = idx & 7;
            cp16(st + row*128 + ((u ^ (row & 7)) << 4),
                 (const char*)g_W1h + ((size_t)row*KD + kt*64 + u*8) * 2);
        }
        cp_commit();
    };
    auto issueB2 = [&](int nc, int stg) {
        uint32_t st = sb + O_BST + stg*16384;
        #pragma unroll
        for (int j = 0; j < 4; j++) {                // 2 planes x 64 rows x 8 units
            int idx = tid + j*256;
            int kc = idx >> 9, rem = idx & 511;
            int row = rem >> 3, u = rem & 7;
            cp16(st + kc*8192 + row*128 + ((u ^ (row & 7)) << 4),
                 (const char*)g_W2h + ((size_t)(nc*64+row)*K2 + kc*64 + u*8) * 2);
        }
        cp_commit();
    };

    for (int t = 0; t < TT; t++) {
        // ---- nw + rms ------------------------------------------------------
        ((float4*)NW)[tid] = ((const float4*)(normsW + (size_t)t*DD))[tid];
        float sum = 0.f;
        #pragma unroll
        for (int kt = 0; kt < 16; kt++) {
            float4 a = *(const float4*)(xr + kt*64 + au*8);
            float4 b = *(const float4*)(xr + kt*64 + au*8 + 4);
            sum += a.x*a.x + a.y*a.y + a.z*a.z + a.w*a.w
                 + b.x*b.x + b.y*b.y + b.z*b.z + b.w*b.w;
        }
        #pragma unroll
        for (int o = 1; o < 8; o <<= 1) sum += __shfl_xor_sync(0xffffffffu, sum, o);
        if (au == 0) RV[arow] = rsqrtf(sum * (1.f/DD) + 1.1920929e-7f);
        issueB1(0, 0); issueB1(1, 1);
        __syncthreads();
        float ri = RV[arow];

        // ---- gemm1: wc = (x*ri*nw) @ W1h^T --------------------------------
        float acc1[4][4] = {};
        #pragma unroll 1
        for (int kt = 0; kt < 16; kt++) {
            {   // convert A k-tile into AH[kt&1]
                float4 a  = *(const float4*)(xr + kt*64 + au*8);
                float4 b  = *(const float4*)(xr + kt*64 + au*8 + 4);
                float4 n0 = *(const float4*)(NW + kt*64 + au*8);
                float4 n1 = *(const float4*)(NW + kt*64 + au*8 + 4);
                __half2 h0{__float2half_rn(a.x*ri*n0.x), __float2half_rn(a.y*ri*n0.y)};
                __half2 h1{__float2half_rn(a.z*ri*n0.z), __float2half_rn(a.w*ri*n0.w)};
                __half2 h2{__float2half_rn(b.x*ri*n1.x), __float2half_rn(b.y*ri*n1.y)};
                __half2 h3{__float2half_rn(b.z*ri*n1.z), __float2half_rn(b.w*ri*n1.w)};
                uint4 pk;
                pk.x = *(uint32_t*)&h0; pk.y = *(uint32_t*)&h1;
                pk.z = *(uint32_t*)&h2; pk.w = *(uint32_t*)&h3;
                *(uint4*)(smem + O_AH + (kt&1)*4096 + arow*128 + ((au ^ (arow&7)) << 4)) = pk;
            }
            if (kt < 15) asm volatile("cp.async.wait_group 1;" ::: "memory");
            else         asm volatile("cp.async.wait_group 0;" ::: "memory");
            __syncthreads();
            if (kt + 2 < 16) issueB1(kt + 2, (kt + 2) % 3);
            uint32_t stA = sb + O_AH + (kt&1)*4096 + rA1*128;
            uint32_t stB = sb + O_BST + (kt%3)*16384 + rB1*128;
            #pragma unroll
            for (int kk = 0; kk < 4; kk++) {
                uint32_t af[4], bf[2][4];
                ldm_x4(af, stA + (((kk*2 + uadd) ^ sA1) << 4));
                #pragma unroll
                for (int nt = 0; nt < 2; nt++)
                    ldm_x4(bf[nt], stB + nt*2048 + (((kk*2 + uadd) ^ sB1) << 4));
                #pragma unroll
                for (int nr = 0; nr < 4; nr++) {
                    uint32_t b2[2] = { bf[nr>>1][nr & 1], bf[nr>>1][(nr & 1) + 2] };
                    mma16816(acc1[nr], af, b2);
                }
            }
            __syncthreads();
        }
        // wc fragments -> smem staging
        {
            int orow = warp_m1*16 + (lane >> 2);
            int ocol = warp_n1*32 + (lane & 3)*2;
            #pragma unroll
            for (int nr = 0; nr < 4; nr++) {
                int cc = ocol + (nr >> 1)*16 + (nr & 1)*8;
                WC[orow*WCP + cc]     = acc1[nr][0];
                WC[orow*WCP + cc + 1] = acc1[nr][1];
                WC[(orow+8)*WCP + cc]     = acc1[nr][2];
                WC[(orow+8)*WCP + cc + 1] = acc1[nr][3];
            }
        }
        __syncthreads();

        // ---- rotate + fp16 convert -> ZH (2 k-planes) ---------------------
        {
            int f0 = au*8;
            const float* wr = WC + arow*WCP;
            float4 a0 = *(const float4*)(wr + f0);
            float4 a1 = *(const float4*)(wr + f0 + 4);
            float4 b0 = *(const float4*)(wr + 64 + f0);
            float4 b1 = *(const float4*)(wr + 64 + f0 + 4);
            float4 c0 = *(const float4*)(TC + arow*64 + f0);
            float4 c1 = *(const float4*)(TC + arow*64 + f0 + 4);
            float4 s0 = *(const float4*)(TS + arow*64 + f0);
            float4 s1 = *(const float4*)(TS + arow*64 + f0 + 4);
            __half2 r0h{__float2half_rn(a0.x*c0.x - b0.x*s0.x), __float2half_rn(a0.y*c0.y - b0.y*s0.y)};
            __half2 r1h{__float2half_rn(a0.z*c0.z - b0.z*s0.z), __float2half_rn(a0.w*c0.w - b0.w*s0.w)};
            __half2 r2h{__float2half_rn(a1.x*c1.x - b1.x*s1.x), __float2half_rn(a1.y*c1.y - b1.y*s1.y)};
            __half2 r3h{__float2half_rn(a1.z*c1.z - b1.z*s1.z), __float2half_rn(a1.w*c1.w - b1.w*s1.w)};
            __half2 i0h{__float2half_rn(a0.x*s0.x + b0.x*c0.x), __float2half_rn(a0.y*s0.y + b0.y*c0.y)};
            __half2 i1h{__float2half_rn(a0.z*s0.z + b0.z*c0.z), __float2half_rn(a0.w*s0.w + b0.w*c0.w)};
            __half2 i2h{__float2half_rn(a1.x*s1.x + b1.x*c1.x), __float2half_rn(a1.y*s1.y + b1.y*c1.y)};
            __half2 i3h{__float2half_rn(a1.z*s1.z + b1.z*c1.z), __float2half_rn(a1.w*s1.w + b1.w*c1.w)};
            uint4 zr, zi;
            zr.x = *(uint32_t*)&r0h; zr.y = *(uint32_t*)&r1h;
            zr.z = *(uint32_t*)&r2h; zr.w = *(uint32_t*)&r3h;
            zi.x = *(uint32_t*)&i0h; zi.y = *(uint32_t*)&i1h;
            zi.z = *(uint32_t*)&i2h; zi.w = *(uint32_t*)&i3h;
            uint32_t zoff = arow*128 + ((au ^ (arow&7)) << 4);
            *(uint4*)(smem + O_ZH + zoff)        = zr;   // k-plane 0 (k=f)
            *(uint4*)(smem + O_ZH + 4096 + zoff) = zi;   // k-plane 1 (k=64+f)
        }
        __syncthreads();

        // ---- gemm2: x += alpha * z @ W2h^T (16 chunks of 64 cols) ---------
        float alpha = 0.1f * __ldg(stepsc + t);
        issueB2(0, 0); issueB2(1, 1);
        #pragma unroll 1
        for (int nc = 0; nc < 16; nc++) {
            if (nc < 15) asm volatile("cp.async.wait_group 1;" ::: "memory");
            else         asm volatile("cp.async.wait_group 0;" ::: "memory");
            __syncthreads();
            if (nc + 2 < 16) issueB2(nc + 2, (nc + 2) % 3);
            float acc2[2][4] = {};
            #pragma unroll
            for (int kc = 0; kc < 2; kc++) {
                uint32_t stA = sb + O_ZH + kc*4096 + rA2*128;
                uint32_t stB = sb + O_BST + (nc%3)*16384 + kc*8192 + rB2*128;
                #pragma unroll
                for (int kk = 0; kk < 4; kk++) {
                    uint32_t af[4], bf[4];
                    ldm_x4(af, stA + (((kk*2 + uadd) ^ sA2) << 4));
                    ldm_x4(bf, stB + (((kk*2 + uadd) ^ sB2) << 4));
                    #pragma unroll
                    for (int nr = 0; nr < 2; nr++) {
                        uint32_t b2[2] = { bf[nr], bf[nr + 2] };
                        mma16816(acc2[nr], af, b2);
                    }
                }
            }
            int orow = warp_m1*16 + (lane >> 2);
            int ocol = nc*64 + warp_n1*16 + (lane & 3)*2;
            #pragma unroll
            for (int nr = 0; nr < 2; nr++) {
                int cc = ocol + nr*8;
                SX[orow*XP + cc]     += alpha*acc2[nr][0];
                SX[orow*XP + cc + 1] += alpha*acc2[nr][1];
                SX[(orow+8)*XP + cc]     += alpha*acc2[nr][2];
                SX[(orow+8)*XP + cc + 1] += alpha*acc2[nr][3];
            }
            __syncthreads();
        }
    }

    // ---- final: rms with out_norm -> g_Xh ---------------------------------
    ((float4*)NW)[tid] = ((const float4*)onw)[tid];
    float sum = 0.f;
    #pragma unroll
    for (int kt = 0; kt < 16; kt++) {
        float4 a = *(const float4*)(xr + kt*64 + au*8);
        float4 b = *(const float4*)(xr + kt*64 + au*8 + 4);
        sum += a.x*a.x + a.y*a.y + a.z*a.z + a.w*a.w
             + b.x*b.x + b.y*b.y + b.z*b.z + b.w*b.w;
    }
    #pragma unroll
    for (int o = 1; o < 8; o <<= 1) sum += __shfl_xor_sync(0xffffffffu, sum, o);
    if (au == 0) RV[arow] = rsqrtf(sum * (1.f/DD) + 1.1920929e-7f);
    __syncthreads();
    float ri = RV[arow];
    #pragma unroll
    for (int kt = 0; kt < 16; kt++) {
        float4 a  = *(const float4*)(xr + kt*64 + au*8);
        float4 b  = *(const float4*)(xr + kt*64 + au*8 + 4);
        float4 n0 = *(const float4*)(NW + kt*64 + au*8);
        float4 n1 = *(const float4*)(NW + kt*64 + au*8 + 4);
        __half2 h0{__float2half_rn(a.x*ri*n0.x), __float2half_rn(a.y*ri*n0.y)};
        __half2 h1{__float2half_rn(a.z*ri*n0.z), __float2half_rn(a.w*ri*n0.w)};
        __half2 h2{__float2half_rn(b.x*ri*n1.x), __float2half_rn(b.y*ri*n1.y)};
        __half2 h3{__float2half_rn(b.z*ri*n1.z), __float2half_rn(b.w*ri*n1.w)};
        uint4 pk;
        pk.x = *(uint32_t*)&h0; pk.y = *(uint32_t*)&h1;
        pk.z = *(uint32_t*)&h2; pk.w = *(uint32_t*)&h3;
        *(uint4*)((char*)g_Xh + ((size_t)(r0+arow)*KD + kt*64 + au*8) * 2) = pk;
    }
}

// ==================== fp16 lm_head GEMM (4-stage) ===========================
#define STAGE_SZ 49152       // A 16K + B 32K
#define NSTG 4
#define NITK (KD/64)         // 16

__global__ void __launch_bounds__(512, 1) k_lm_mma(float* __restrict__ out) {
    extern __shared__ __align__(128) char smem[];
    uint32_t sb = smem_u32(smem);
    int tid = threadIdx.x;
    int lane = tid & 31, wid = tid >> 5;
    int warp_m = wid & 3, warp_n = wid >> 2;
    int r0 = blockIdx.x * 128;      // M fastest: A stays L2-resident, B streams once
    int n0 = blockIdx.y * 256;

    const char* srcA = (const char*)g_Xh + ((size_t)r0 * KD) * 2;
    const char* srcB = (const char*)g_Wh + ((size_t)n0 * KD) * 2;

    int lrow = ((lane >> 3) & 1) * 8 + (lane & 7);
    int uadd = lane >> 4;
    int rA = warp_m * 32 + lrow;
    int rB = warp_n * 64 + lrow;
    int sA = rA & 7, sB = rB & 7;
    uint32_t aBase = sb + rA * 128;
    uint32_t bBase = sb + 16384 + rB * 128;

    float acc[2][8][4] = {};

    auto issue = [&](int kt, int stg) {
        uint32_t st = sb + stg * STAGE_SZ;
        #pragma unroll
        for (int j = 0; j < 2; j++) {
            int idx = tid + j*512;
            int row = idx >> 3, u = idx & 7;
            cp16(st + row*128 + ((u ^ (row & 7)) << 4),
                 srcA + ((size_t)row*KD + kt*64 + u*8) * 2);
        }
        #pragma unroll
        for (int j = 0; j < 4; j++) {
            int idx = tid + j*512;
            int row = idx >> 3, u = idx & 7;
            cp16(st + 16384 + row*128 + ((u ^ (row & 7)) << 4),
                 srcB + ((size_t)row*KD + kt*64 + u*8) * 2);
        }
        cp_commit();
    };

    issue(0, 0); issue(1, 1); issue(2, 2);

    for (int kt = 0; kt < NITK; kt++) {
        if (kt < NITK-2)      asm volatile("cp.async.wait_group 2;" ::: "memory");
        else if (kt < NITK-1) asm volatile("cp.async.wait_group 1;" ::: "memory");
        else                  asm volatile("cp.async.wait_group 0;" ::: "memory");
        __syncthreads();
        if (kt + 3 < NITK) issue(kt + 3, (kt + 3) & 3);

        uint32_t stA = aBase + (kt & 3) * STAGE_SZ;
        uint32_t stB = bBase + (kt & 3) * STAGE_SZ;
        #pragma unroll
        for (int kk = 0; kk < 4; kk++) {
            uint32_t af[2][4], bf[4][4];
            #pragma unroll
            for (int mt = 0; mt < 2; mt++)
                ldm_x4(af[mt], stA + mt*2048 + (((kk*2 + uadd) ^ sA) << 4));
            #pragma unroll
            for (int nt = 0; nt < 4; nt++)
                ldm_x4(bf[nt], stB + nt*2048 + (((kk*2 + uadd) ^ sB) << 4));
            #pragma unroll
            for (int mt = 0; mt < 2; mt++)
                #pragma unroll
                for (int nr = 0; nr < 8; nr++) {
                    uint32_t b2[2] = { bf[nr>>1][nr & 1], bf[nr>>1][(nr & 1) + 2] };
                    mma16816(acc[mt][nr], af[mt], b2);
                }
        }
        __syncthreads();
    }

    int orow = r0 + warp_m*32 + (lane >> 2);
    int ocol = n0 + warp_n*64 + (lane & 3)*2;
    #pragma unroll
    for (int mt = 0; mt < 2; mt++) {
        #pragma unroll
        for (int nr = 0; nr < 8; nr++) {
            int cc = ocol + (nr >> 1)*16 + (nr & 1)*8;
            size_t p0 = (size_t)(orow + mt*16)     * VV + cc;
            size_t p1 = (size_t)(orow + mt*16 + 8) * VV + cc;
            if (cc < VV)     { out[p0]   = acc[mt][nr][0]; out[p1]   = acc[mt][nr][2]; }
            if (cc + 1 < VV) { out[p0+1] = acc[mt][nr][1]; out[p1+1] = acc[mt][nr][3]; }
        }
    }
}

// ==================== launch ================================================
extern "C" void kernel_launch(void* const* d_in, const int* in_sizes, int n_in,
                              void* d_out, int out_size) {
    const int*   tokens   = (const int*)  d_in[0];
    const float* embW     = (const float*)d_in[1];
    const float* toW      = (const float*)d_in[2];
    const float* fwW      = (const float*)d_in[3];
    const float* speed    = (const float*)d_in[4];
    const float* dampen   = (const float*)d_in[5];
    const float* phase    = (const float*)d_in[6];
    const float* coupling = (const float*)d_in[7];
    const float* stepsc   = (const float*)d_in[8];
    const float* posf     = (const float*)d_in[9];
    const float* normsW   = (const float*)d_in[10];
    const float* onw      = (const float*)d_in[11];
    const float* lmW      = (const float*)d_in[12];
    float* out = (float*)d_out;

    cudaFuncSetAttribute(k_lm_mma, cudaFuncAttributeMaxDynamicSharedMemorySize, NSTG*STAGE_SZ);
    cudaFuncSetAttribute(k_step,   cudaFuncAttributeMaxDynamicSharedMemorySize, STEP_SMEM);

    k_prep_w2h<<<(DD*K2 + 255)/256, 256>>>(speed, dampen, phase, coupling, fwW);
    k_convW1h<<<2*FF, 256>>>(toW);
    k_tables<<<(SS*FF + 255)/256, 256>>>(posf);
    k_embed<<<MM, 256>>>(tokens, embW);
    k_convWh<<<NPAD, 256>>>(lmW);

    k_step<<<MM/RPC, 256, STEP_SMEM>>>(normsW, stepsc, onw);

    k_lm_mma<<<dim3(MM/128, NPAD/256), 512, NSTG*STAGE_SZ>>>(out);
}

// round 12
// speedup vs baseline: 5.6594x; 1.0087x over previous
#include <cuda_runtime.h>
#include <cuda_fp16.h>
#include <math.h>
#include <math_constants.h>
#include <cstdint>

#define BB 2
#define SS 2048
#define DD 1024
#define FF 64
#define TT 28
#define VV 50257
#define MM (BB*SS)      // 4096
#define NPAD 50432      // 197 * 256
#define KD 1024
#define K2 128
#define RPC 32          // rows per CTA in the persistent step kernel
#define XP 1032         // padded sx row pitch (floats) — bank rotation

// ==================== scratch (device globals; no allocation) ===============
__device__ float g_x[(size_t)MM*DD];
__device__ float g_ct[(size_t)SS*FF];
__device__ float g_st[(size_t)SS*FF];
__device__ unsigned short g_Xh[(size_t)MM*KD];     // fp16 normed x (lm A)
__device__ unsigned short g_Wh[(size_t)NPAD*KD];   // fp16 lm_head W
__device__ unsigned short g_W1h[(size_t)2*FF*KD];  // fp16 to_wave_W [128,1024]
__device__ unsigned short g_W2h[(size_t)DD*K2];    // fp16 W2^T      [1024,128]

// ==================== helpers ===============================================
__device__ __forceinline__ uint32_t smem_u32(const void* p) {
    uint32_t a;
    asm("{ .reg .u64 t; cvta.to.shared.u64 t, %1; cvt.u32.u64 %0, t; }" : "=r"(a) : "l"(p));
    return a;
}
__device__ __forceinline__ void cp16(uint32_t dst, const void* src) {
    asm volatile("cp.async.cg.shared.global [%0], [%1], 16;\n" :: "r"(dst), "l"(src) : "memory");
}
__device__ __forceinline__ void cp_commit() { asm volatile("cp.async.commit_group;\n" ::: "memory"); }

__device__ __forceinline__ void ldm_x4(uint32_t* r, uint32_t addr) {
    asm volatile("ldmatrix.sync.aligned.m8n8.x4.shared.b16 {%0,%1,%2,%3}, [%4];"
        : "=r"(r[0]), "=r"(r[1]), "=r"(r[2]), "=r"(r[3]) : "r"(addr));
}
__device__ __forceinline__ void mma16816(float* d, const uint32_t* a, const uint32_t* b) {
    asm volatile("mma.sync.aligned.m16n8k16.row.col.f32.f16.f16.f32 "
        "{%0,%1,%2,%3}, {%4,%5,%6,%7}, {%8,%9}, {%0,%1,%2,%3};"
        : "+f"(d[0]), "+f"(d[1]), "+f"(d[2]), "+f"(d[3])
        : "r"(a[0]), "r"(a[1]), "r"(a[2]), "r"(a[3]), "r"(b[0]), "r"(b[1]));
}

// ==================== one-time precompute ===================================
__global__ void k_prep_w2h(const float* __restrict__ speed,
                           const float* __restrict__ dampen,
                           const float* __restrict__ phase,
                           const float* __restrict__ coupling,
                           const float* __restrict__ fwW) {
    int idx = blockIdx.x * blockDim.x + threadIdx.x;
    if (idx >= DD*K2) return;
    int d = idx >> 7, j = idx & 127;
    int f = j & (FF-1);
    float dmp = dampen[f];
    float sp  = (dmp > 20.f) ? dmp : log1pf(expf(dmp));
    float m   = expf(-sp);
    float th  = speed[f] * CUDART_PI_F + phase[f];
    float c, s; sincosf(th, &s, &c);
    float coef = (j < FF) ? (m * c) : (-m * s);
    float acc = 0.f;
    #pragma unroll 8
    for (int g = 0; g < FF; g++) acc += coupling[f*FF+g] * fwW[d*FF+g];
    ((__half*)g_W2h)[idx] = __float2half_rn(coef * acc);
}

__global__ void k_convW1h(const float* __restrict__ toW) {
    int f = blockIdx.x;
    int tid = threadIdx.x;
    float4 w = *(const float4*)(toW + (size_t)f*DD + tid*4);
    __half2* p = (__half2*)(g_W1h + (size_t)f*KD + tid*4);
    p[0] = __half2{__float2half_rn(w.x), __float2half_rn(w.y)};
    p[1] = __half2{__float2half_rn(w.z), __float2half_rn(w.w)};
}

__global__ void k_tables(const float* __restrict__ pf) {
    int idx = blockIdx.x * blockDim.x + threadIdx.x;
    if (idx >= SS*FF) return;
    int s = idx / FF, f = idx - s*FF;
    float th = (float)s * pf[f];
    float sn, cs; sincosf(th, &sn, &cs);
    g_ct[idx] = cs;
    g_st[idx] = sn;
}

__global__ void k_embed(const int* __restrict__ tokens,
                        const float* __restrict__ embW) {
    int r = blockIdx.x;
    int t = tokens[r];
    const float4* src = (const float4*)(embW + (size_t)t * DD);
    float4* dst = (float4*)(g_x + (size_t)r * DD);
    dst[threadIdx.x] = src[threadIdx.x];
}

__global__ void k_convWh(const float* __restrict__ lmW) {
    int v = blockIdx.x;
    int tid = threadIdx.x;
    float4 w = make_float4(0.f, 0.f, 0.f, 0.f);
    if (v < VV) w = *(const float4*)(lmW + (size_t)v*DD + tid*4);
    __half2* p = (__half2*)(g_Wh + (size_t)v*KD + tid*4);
    p[0] = __half2{__float2half_rn(w.x), __float2half_rn(w.y)};
    p[1] = __half2{__float2half_rn(w.z), __float2half_rn(w.w)};
}

// ==================== persistent step kernel ================================
// 128 CTAs x 256 threads; each CTA owns 32 rows of x resident in smem for all
// 28 steps. Minimal-barrier pipelines: 1 sync per k-iteration (3-stage B ring
// + double-buffered A-convert make the second sync provably redundant).
//
// smem layout (bytes):
#define O_SX    0                         // 32 x 1032 fp32 = 132096
#define O_TC    132096                    // ct 32x64 fp32  = 8192
#define O_TS    140288                    // st 32x64 fp32  = 8192
#define O_NW    148480                    // nw 1024 fp32   = 4096
#define O_RV    152576                    // rinv 32 fp32   = 128
#define O_ZH    152704                    // z fp16 2 planes x 32x128B = 8192
#define O_AH    160896                    // A fp16 ktile x2 = 8192
#define O_BST   169088                    // B staging 3 x 16384 = 49152
#define STEP_SMEM 218240
#define WCP 132                           // wc staging pitch (floats), in BST

__global__ void __launch_bounds__(256, 1)
k_step(const float* __restrict__ normsW,
       const float* __restrict__ stepsc,
       const float* __restrict__ onw) {
    extern __shared__ __align__(128) char smem[];
    uint32_t sb = smem_u32(smem);
    float* SX  = (float*)smem;
    float* TC  = (float*)(smem + O_TC);
    float* TS  = (float*)(smem + O_TS);
    float* NW  = (float*)(smem + O_NW);
    float* RV  = (float*)(smem + O_RV);
    float* WC  = (float*)(smem + O_BST);   // wc staging reuses B region

    int tid = threadIdx.x, lane = tid & 31, wid = tid >> 5;
    int r0 = blockIdx.x * RPC;
    int arow = tid >> 3, au = tid & 7;     // 8 threads per owned row

    // ---- init: x rows + rotation tables into smem -------------------------
    for (int i = tid; i < RPC*256; i += 256) {       // 8192 float4
        int row = i >> 8, c4 = i & 255;
        *(float4*)(SX + (size_t)row*XP + c4*4) =
            ((const float4*)(g_x + (size_t)(r0+row)*DD))[c4];
    }
    for (int i = tid; i < RPC*FF; i += 256) {
        int row = i >> 6, f = i & 63;
        int s = (r0 + row) & (SS-1);
        TC[i] = g_ct[(size_t)s*FF + f];
        TS[i] = g_st[(size_t)s*FF + f];
    }
    __syncthreads();

    // gemm1/gemm2 warp layout: 2 warp_m x 4 warp_n
    int warp_m1 = wid & 1, warp_n1 = wid >> 1;
    int lrow = ((lane >> 3) & 1) * 8 + (lane & 7);
    int uadd = lane >> 4;
    int rA1 = warp_m1*16 + lrow, sA1 = rA1 & 7;
    int rB1 = warp_n1*32 + lrow, sB1 = rB1 & 7;
    int rA2 = warp_m1*16 + lrow, sA2 = rA2 & 7;
    int rB2 = warp_n1*16 + lrow, sB2 = rB2 & 7;

    const float* xr = SX + (size_t)arow*XP;

    auto issueB1 = [&](int kt, int stg) {
        uint32_t st = sb + O_BST + stg*16384;
        #pragma unroll
        for (int j = 0; j < 4; j++) {                // 128 rows x 8 units
            int idx = tid + j*256; int row = idx >> 3, u = idx & 7;
            cp16(st + row*128 + ((u ^ (row & 7)) << 4),
                 (const char*)g_W1h + ((size_t)row*KD + kt*64 + u*8) * 2);
        }
        cp_commit();
    };
    auto issueB2 = [&](int nc, int stg) {
        uint32_t st = sb + O_BST + stg*16384;
        #pragma unroll
        for (int j = 0; j < 4; j++) {                // 2 planes x 64 rows x 8 units
            int idx = tid + j*256;
            int kc = idx >> 9, rem = idx & 511;
            int row = rem >> 3, u = rem & 7;
            cp16(st + kc*8192 + row*128 + ((u ^ (row & 7)) << 4),
                 (const char*)g_W2h + ((size_t)(nc*64+row)*K2 + kc*64 + u*8) * 2);
        }
        cp_commit();
    };

    for (int t = 0; t < TT; t++) {
        // ---- nw + rms ------------------------------------------------------
        ((float4*)NW)[tid] = ((const float4*)(normsW + (size_t)t*DD))[tid];
        float sum = 0.f;
        #pragma unroll
        for (int kt = 0; kt < 16; kt++) {
            float4 a = *(const float4*)(xr + kt*64 + au*8);
            float4 b = *(const float4*)(xr + kt*64 + au*8 + 4);
            sum += a.x*a.x + a.y*a.y + a.z*a.z + a.w*a.w
                 + b.x*b.x + b.y*b.y + b.z*b.z + b.w*b.w;
        }
        #pragma unroll
        for (int o = 1; o < 8; o <<= 1) sum += __shfl_xor_sync(0xffffffffu, sum, o);
        if (au == 0) RV[arow] = rsqrtf(sum * (1.f/DD) + 1.1920929e-7f);
        issueB1(0, 0); issueB1(1, 1);
        __syncthreads();                              // S: RV + NW visible
        float ri = RV[arow];

        // ---- gemm1: wc = (x*ri*nw) @ W1h^T  (1 sync per iter) -------------
        // Invariant: all passed S(kt) => all completed C(kt) and M(kt-1).
        // Hence C(kt+1) may overwrite AH[(kt+1)&1] (last read by M(kt-1)),
        // and issue(kt+2) may overwrite stage (kt-1)%3 (last read by M(kt-1)).
        float acc1[4][4] = {};
        #pragma unroll 1
        for (int kt = 0; kt < 16; kt++) {
            {   // C(kt): convert A k-tile into AH[kt&1]
                float4 a  = *(const float4*)(xr + kt*64 + au*8);
                float4 b  = *(const float4*)(xr + kt*64 + au*8 + 4);
                float4 n0 = *(const float4*)(NW + kt*64 + au*8);
                float4 n1 = *(const float4*)(NW + kt*64 + au*8 + 4);
                __half2 h0{__float2half_rn(a.x*ri*n0.x), __float2half_rn(a.y*ri*n0.y)};
                __half2 h1{__float2half_rn(a.z*ri*n0.z), __float2half_rn(a.w*ri*n0.w)};
                __half2 h2{__float2half_rn(b.x*ri*n1.x), __float2half_rn(b.y*ri*n1.y)};
                __half2 h3{__float2half_rn(b.z*ri*n1.z), __float2half_rn(b.w*ri*n1.w)};
                uint4 pk;
                pk.x = *(uint32_t*)&h0; pk.y = *(uint32_t*)&h1;
                pk.z = *(uint32_t*)&h2; pk.w = *(uint32_t*)&h3;
                *(uint4*)(smem + O_AH + (kt&1)*4096 + arow*128 + ((au ^ (arow&7)) << 4)) = pk;
            }
            if (kt < 15) asm volatile("cp.async.wait_group 1;" ::: "memory");
            else         asm volatile("cp.async.wait_group 0;" ::: "memory");
            __syncthreads();                          // S(kt)
            if (kt + 2 < 16) issueB1(kt + 2, (kt + 2) % 3);
            uint32_t stA = sb + O_AH + (kt&1)*4096 + rA1*128;
            uint32_t stB = sb + O_BST + (kt%3)*16384 + rB1*128;
            #pragma unroll
            for (int kk = 0; kk < 4; kk++) {          // M(kt)
                uint32_t af[4], bf[2][4];
                ldm_x4(af, stA + (((kk*2 + uadd) ^ sA1) << 4));
                #pragma unroll
                for (int nt = 0; nt < 2; nt++)
                    ldm_x4(bf[nt], stB + nt*2048 + (((kk*2 + uadd) ^ sB1) << 4));
                #pragma unroll
                for (int nr = 0; nr < 4; nr++) {
                    uint32_t b2[2] = { bf[nr>>1][nr & 1], bf[nr>>1][(nr & 1) + 2] };
                    mma16816(acc1[nr], af, b2);
                }
            }
        }
        __syncthreads();                              // M(15) done; WC region free

        // wc fragments -> smem staging
        {
            int orow = warp_m1*16 + (lane >> 2);
            int ocol = warp_n1*32 + (lane & 3)*2;
            #pragma unroll
            for (int nr = 0; nr < 4; nr++) {
                int cc = ocol + (nr >> 1)*16 + (nr & 1)*8;
                WC[orow*WCP + cc]     = acc1[nr][0];
                WC[orow*WCP + cc + 1] = acc1[nr][1];
                WC[(orow+8)*WCP + cc]     = acc1[nr][2];
                WC[(orow+8)*WCP + cc + 1] = acc1[nr][3];
            }
        }
        __syncthreads();                              // WC visible

        // ---- rotate + fp16 convert -> ZH (2 k-planes) ---------------------
        {
            int f0 = au*8;
            const float* wr = WC + arow*WCP;
            float4 a0 = *(const float4*)(wr + f0);
            float4 a1 = *(const float4*)(wr + f0 + 4);
            float4 b0 = *(const float4*)(wr + 64 + f0);
            float4 b1 = *(const float4*)(wr + 64 + f0 + 4);
            float4 c0 = *(const float4*)(TC + arow*64 + f0);
            float4 c1 = *(const float4*)(TC + arow*64 + f0 + 4);
            float4 s0 = *(const float4*)(TS + arow*64 + f0);
            float4 s1 = *(const float4*)(TS + arow*64 + f0 + 4);
            __half2 r0h{__float2half_rn(a0.x*c0.x - b0.x*s0.x), __float2half_rn(a0.y*c0.y - b0.y*s0.y)};
            __half2 r1h{__float2half_rn(a0.z*c0.z - b0.z*s0.z), __float2half_rn(a0.w*c0.w - b0.w*s0.w)};
            __half2 r2h{__float2half_rn(a1.x*c1.x - b1.x*s1.x), __float2half_rn(a1.y*c1.y - b1.y*s1.y)};
            __half2 r3h{__float2half_rn(a1.z*c1.z - b1.z*s1.z), __float2half_rn(a1.w*c1.w - b1.w*s1.w)};
            __half2 i0h{__float2half_rn(a0.x*s0.x + b0.x*c0.x), __float2half_rn(a0.y*s0.y + b0.y*c0.y)};
            __half2 i1h{__float2half_rn(a0.z*s0.z + b0.z*c0.z), __float2half_rn(a0.w*s0.w + b0.w*c0.w)};
            __half2 i2h{__float2half_rn(a1.x*s1.x + b1.x*c1.x), __float2half_rn(a1.y*s1.y + b1.y*c1.y)};
            __half2 i3h{__float2half_rn(a1.z*s1.z + b1.z*c1.z), __float2half_rn(a1.w*s1.w + b1.w*c1.w)};
            uint4 zr, zi;
            zr.x = *(uint32_t*)&r0h; zr.y = *(uint32_t*)&r1h;
            zr.z = *(uint32_t*)&r2h; zr.w = *(uint32_t*)&r3h;
            zi.x = *(uint32_t*)&i0h; zi.y = *(uint32_t*)&i1h;
            zi.z = *(uint32_t*)&i2h; zi.w = *(uint32_t*)&i3h;
            uint32_t zoff = arow*128 + ((au ^ (arow&7)) << 4);
            *(uint4*)(smem + O_ZH + zoff)        = zr;
            *(uint4*)(smem + O_ZH + 4096 + zoff) = zi;
        }
        __syncthreads();                              // ZH visible; WC free

        // ---- gemm2: x += alpha * z @ W2h^T (1 sync per chunk) -------------
        float alpha = 0.1f * __ldg(stepsc + t);
        issueB2(0, 0); issueB2(1, 1);
        #pragma unroll 1
        for (int nc = 0; nc < 16; nc++) {
            if (nc < 15) asm volatile("cp.async.wait_group 1;" ::: "memory");
            else         asm volatile("cp.async.wait_group 0;" ::: "memory");
            __syncthreads();                          // S(nc)
            if (nc + 2 < 16) issueB2(nc + 2, (nc + 2) % 3);
            float acc2[2][4] = {};
            #pragma unroll
            for (int kc = 0; kc < 2; kc++) {          // M(nc)
                uint32_t stA = sb + O_ZH + kc*4096 + rA2*128;
                uint32_t stB = sb + O_BST + (nc%3)*16384 + kc*8192 + rB2*128;
                #pragma unroll
                for (int kk = 0; kk < 4; kk++) {
                    uint32_t af[4], bf[4];
                    ldm_x4(af, stA + (((kk*2 + uadd) ^ sA2) << 4));
                    ldm_x4(bf, stB + (((kk*2 + uadd) ^ sB2) << 4));
                    #pragma unroll
                    for (int nr = 0; nr < 2; nr++) {
                        uint32_t b2[2] = { bf[nr], bf[nr + 2] };
                        mma16816(acc2[nr], af, b2);
                    }
                }
            }
            int orow = warp_m1*16 + (lane >> 2);      // epi(nc): writes SX only
            int ocol = nc*64 + warp_n1*16 + (lane & 3)*2;
            #pragma unroll
            for (int nr = 0; nr < 2; nr++) {
                int cc = ocol + nr*8;
                SX[orow*XP + cc]     += alpha*acc2[nr][0];
                SX[orow*XP + cc + 1] += alpha*acc2[nr][1];
                SX[(orow+8)*XP + cc]     += alpha*acc2[nr][2];
                SX[(orow+8)*XP + cc + 1] += alpha*acc2[nr][3];
            }
        }
        __syncthreads();                              // step end: SX consistent
    }

    // ---- final: rms with out_norm -> g_Xh ---------------------------------
    ((float4*)NW)[tid] = ((const float4*)onw)[tid];
    float sum = 0.f;
    #pragma unroll
    for (int kt = 0; kt < 16; kt++) {
        float4 a = *(const float4*)(xr + kt*64 + au*8);
        float4 b = *(const float4*)(xr + kt*64 + au*8 + 4);
        sum += a.x*a.x + a.y*a.y + a.z*a.z + a.w*a.w
             + b.x*b.x + b.y*b.y + b.z*b.z + b.w*b.w;
    }
    #pragma unroll
    for (int o = 1; o < 8; o <<= 1) sum += __shfl_xor_sync(0xffffffffu, sum, o);
    if (au == 0) RV[arow] = rsqrtf(sum * (1.f/DD) + 1.1920929e-7f);
    __syncthreads();
    float ri = RV[arow];
    #pragma unroll
    for (int kt = 0; kt < 16; kt++) {
        float4 a  = *(const float4*)(xr + kt*64 + au*8);
        float4 b  = *(const float4*)(xr + kt*64 + au*8 + 4);
        float4 n0 = *(const float4*)(NW + kt*64 + au*8);
        float4 n1 = *(const float4*)(NW + kt*64 + au*8 + 4);
        __half2 h0{__float2half_rn(a.x*ri*n0.x), __float2half_rn(a.y*ri*n0.y)};
        __half2 h1{__float2half_rn(a.z*ri*n0.z), __float2half_rn(a.w*ri*n0.w)};
        __half2 h2{__float2half_rn(b.x*ri*n1.x), __float2half_rn(b.y*ri*n1.y)};
        __half2 h3{__float2half_rn(b.z*ri*n1.z), __float2half_rn(b.w*ri*n1.w)};
        uint4 pk;
        pk.x = *(uint32_t*)&h0; pk.y = *(uint32_t*)&h1;
        pk.z = *(uint32_t*)&h2; pk.w = *(uint32_t*)&h3;
        *(uint4*)((char*)g_Xh + ((size_t)(r0+arow)*KD + kt*64 + au*8) * 2) = pk;
    }
}

// ==================== fp16 lm_head GEMM (4-stage) ===========================
#define STAGE_SZ 49152       // A 16K + B 32K
#define NSTG 4
#define NITK (KD/64)         // 16

__global__ void __launch_bounds__(512, 1) k_lm_mma(float* __restrict__ out) {
    extern __shared__ __align__(128) char smem[];
    uint32_t sb = smem_u32(smem);
    int tid = threadIdx.x;
    int lane = tid & 31, wid = tid >> 5;
    int warp_m = wid & 3, warp_n = wid >> 2;
    int r0 = blockIdx.x * 128;      // M fastest: A stays L2-resident, B streams once
    int n0 = blockIdx.y * 256;

    const char* srcA = (const char*)g_Xh + ((size_t)r0 * KD) * 2;
    const char* srcB = (const char*)g_Wh + ((size_t)n0 * KD) * 2;

    int lrow = ((lane >> 3) & 1) * 8 + (lane & 7);
    int uadd = lane >> 4;
    int rA = warp_m * 32 + lrow;
    int rB = warp_n * 64 + lrow;
    int sA = rA & 7, sB = rB & 7;
    uint32_t aBase = sb + rA * 128;
    uint32_t bBase = sb + 16384 + rB * 128;

    float acc[2][8][4] = {};

    auto issue = [&](int kt, int stg) {
        uint32_t st = sb + stg * STAGE_SZ;
        #pragma unroll
        for (int j = 0; j < 2; j++) {
            int idx = tid + j*512;
            int row = idx >> 3, u = idx & 7;
            cp16(st + row*128 + ((u ^ (row & 7)) << 4),
                 srcA + ((size_t)row*KD + kt*64 + u*8) * 2);
        }
        #pragma unroll
        for (int j = 0; j < 4; j++) {
            int idx = tid + j*512;
            int row = idx >> 3, u = idx & 7;
            cp16(st + 16384 + row*128 + ((u ^ (row & 7)) << 4),
                 srcB + ((size_t)row*KD + kt*64 + u*8) * 2);
        }
        cp_commit();
    };

    issue(0, 0); issue(1, 1); issue(2, 2);

    for (int kt = 0; kt < NITK; kt++) {
        if (kt < NITK-2)      asm volatile("cp.async.wait_group 2;" ::: "memory");
        else if (kt < NITK-1) asm volatile("cp.async.wait_group 1;" ::: "memory");
        else                  asm volatile("cp.async.wait_group 0;" ::: "memory");
        __syncthreads();
        if (kt + 3 < NITK) issue(kt + 3, (kt + 3) & 3);

        uint32_t stA = aBase + (kt & 3) * STAGE_SZ;
        uint32_t stB = bBase + (kt & 3) * STAGE_SZ;
        #pragma unroll
        for (int kk = 0; kk < 4; kk++) {
            uint32_t af[2][4], bf[4][4];
            #pragma unroll
            for (int mt = 0; mt < 2; mt++)
                ldm_x4(af[mt], stA + mt*2048 + (((kk*2 + uadd) ^ sA) << 4));
            #pragma unroll
            for (int nt = 0; nt < 4; nt++)
                ldm_x4(bf[nt], stB + nt*2048 + (((kk*2 + uadd) ^ sB) << 4));
            #pragma unroll
            for (int mt = 0; mt < 2; mt++)
                #pragma unroll
                for (int nr = 0; nr < 8; nr++) {
                    uint32_t b2[2] = { bf[nr>>1][nr & 1], bf[nr>>1][(nr & 1) + 2] };
                    mma16816(acc[mt][nr], af[mt], b2);
                }
        }
        __syncthreads();
    }

    int orow = r0 + warp_m*32 + (lane >> 2);
    int ocol = n0 + warp_n*64 + (lane & 3)*2;
    #pragma unroll
    for (int mt = 0; mt < 2; mt++) {
        #pragma unroll
        for (int nr = 0; nr < 8; nr++) {
            int cc = ocol + (nr >> 1)*16 + (nr & 1)*8;
            size_t p0 = (size_t)(orow + mt*16)     * VV + cc;
            size_t p1 = (size_t)(orow + mt*16 + 8) * VV + cc;
            if (cc < VV)     { out[p0]   = acc[mt][nr][0]; out[p1]   = acc[mt][nr][2]; }
            if (cc + 1 < VV) { out[p0+1] = acc[mt][nr][1]; out[p1+1] = acc[mt][nr][3]; }
        }
    }
}

// ==================== launch ================================================
extern "C" void kernel_launch(void* const* d_in, const int* in_sizes, int n_in,
                              void* d_out, int out_size) {
    const int*   tokens   = (const int*)  d_in[0];
    const float* embW     = (const float*)d_in[1];
    const float* toW      = (const float*)d_in[2];
    const float* fwW      = (const float*)d_in[3];
    const float* speed    = (const float*)d_in[4];
    const float* dampen   = (const float*)d_in[5];
    const float* phase    = (const float*)d_in[6];
    const float* coupling = (const float*)d_in[7];
    const float* stepsc   = (const float*)d_in[8];
    const float* posf     = (const float*)d_in[9];
    const float* normsW   = (const float*)d_in[10];
    const float* onw      = (const float*)d_in[11];
    const float* lmW      = (const float*)d_in[12];
    float* out = (float*)d_out;

    cudaFuncSetAttribute(k_lm_mma, cudaFuncAttributeMaxDynamicSharedMemorySize, NSTG*STAGE_SZ);
    cudaFuncSetAttribute(k_step,   cudaFuncAttributeMaxDynamicSharedMemorySize, STEP_SMEM);

    k_prep_w2h<<<(DD*K2 + 255)/256, 256>>>(speed, dampen, phase, coupling, fwW);
    k_convW1h<<<2*FF, 256>>>(toW);
    k_tables<<<(SS*FF + 255)/256, 256>>>(posf);
    k_embed<<<MM, 256>>>(tokens, embW);
    k_convWh<<<NPAD, 256>>>(lmW);

    k_step<<<MM/RPC, 256, STEP_SMEM>>>(normsW, stepsc, onw);

    k_lm_mma<<<dim3(MM/128, NPAD/256), 512, NSTG*STAGE_SZ>>>(out);
}

// round 13
// speedup vs baseline: 5.7177x; 1.0103x over previous
#include <cuda_runtime.h>
#include <cuda_fp16.h>
#include <math.h>
#include <math_constants.h>
#include <cstdint>

#define BB 2
#define SS 2048
#define DD 1024
#define FF 64
#define TT 28
#define VV 50257
#define MM (BB*SS)      // 4096
#define NPAD 50432      // 197 * 256
#define KD 1024
#define K2 128
#define RPC 32          // rows per CTA in the persistent step kernel
#define XP 1032         // padded sx row pitch (floats)

// ==================== scratch (device globals; no allocation) ===============
__device__ float g_x[(size_t)MM*DD];
__device__ float g_ct[(size_t)SS*FF];
__device__ float g_st[(size_t)SS*FF];
__device__ unsigned short g_Xh[(size_t)MM*KD];     // fp16 normed x (lm A)
__device__ unsigned short g_Wh[(size_t)NPAD*KD];   // fp16 lm_head W
__device__ unsigned short g_W1h[(size_t)2*FF*KD];  // fp16 to_wave_W [128,1024]
__device__ unsigned short g_W2h[(size_t)DD*K2];    // fp16 W2^T      [1024,128]

// ==================== helpers ===============================================
__device__ __forceinline__ uint32_t smem_u32(const void* p) {
    uint32_t a;
    asm("{ .reg .u64 t; cvta.to.shared.u64 t, %1; cvt.u32.u64 %0, t; }" : "=r"(a) : "l"(p));
    return a;
}
__device__ __forceinline__ void cp16(uint32_t dst, const void* src) {
    asm volatile("cp.async.cg.shared.global [%0], [%1], 16;\n" :: "r"(dst), "l"(src) : "memory");
}
__device__ __forceinline__ void cp_commit() { asm volatile("cp.async.commit_group;\n" ::: "memory"); }

__device__ __forceinline__ void ldm_x4(uint32_t* r, uint32_t addr) {
    asm volatile("ldmatrix.sync.aligned.m8n8.x4.shared.b16 {%0,%1,%2,%3}, [%4];"
        : "=r"(r[0]), "=r"(r[1]), "=r"(r[2]), "=r"(r[3]) : "r"(addr));
}
__device__ __forceinline__ void mma16816(float* d, const uint32_t* a, const uint32_t* b) {
    asm volatile("mma.sync.aligned.m16n8k16.row.col.f32.f16.f16.f32 "
        "{%0,%1,%2,%3}, {%4,%5,%6,%7}, {%8,%9}, {%0,%1,%2,%3};"
        : "+f"(d[0]), "+f"(d[1]), "+f"(d[2]), "+f"(d[3])
        : "r"(a[0]), "r"(a[1]), "r"(a[2]), "r"(a[3]), "r"(b[0]), "r"(b[1]));
}

// ==================== one-time precompute ===================================
__global__ void k_prep_w2h(const float* __restrict__ speed,
                           const float* __restrict__ dampen,
                           const float* __restrict__ phase,
                           const float* __restrict__ coupling,
                           const float* __restrict__ fwW) {
    int idx = blockIdx.x * blockDim.x + threadIdx.x;
    if (idx >= DD*K2) return;
    int d = idx >> 7, j = idx & 127;
    int f = j & (FF-1);
    float dmp = dampen[f];
    float sp  = (dmp > 20.f) ? dmp : log1pf(expf(dmp));
    float m   = expf(-sp);
    float th  = speed[f] * CUDART_PI_F + phase[f];
    float c, s; sincosf(th, &s, &c);
    float coef = (j < FF) ? (m * c) : (-m * s);
    float acc = 0.f;
    #pragma unroll 8
    for (int g = 0; g < FF; g++) acc += coupling[f*FF+g] * fwW[d*FF+g];
    ((__half*)g_W2h)[idx] = __float2half_rn(coef * acc);
}

__global__ void k_convW1h(const float* __restrict__ toW) {
    int f = blockIdx.x;
    int tid = threadIdx.x;
    float4 w = *(const float4*)(toW + (size_t)f*DD + tid*4);
    __half2* p = (__half2*)(g_W1h + (size_t)f*KD + tid*4);
    p[0] = __half2{__float2half_rn(w.x), __float2half_rn(w.y)};
    p[1] = __half2{__float2half_rn(w.z), __float2half_rn(w.w)};
}

__global__ void k_tables(const float* __restrict__ pf) {
    int idx = blockIdx.x * blockDim.x + threadIdx.x;
    if (idx >= SS*FF) return;
    int s = idx / FF, f = idx - s*FF;
    float th = (float)s * pf[f];
    float sn, cs; sincosf(th, &sn, &cs);
    g_ct[idx] = cs;
    g_st[idx] = sn;
}

__global__ void k_embed(const int* __restrict__ tokens,
                        const float* __restrict__ embW) {
    int r = blockIdx.x;
    int t = tokens[r];
    const float4* src = (const float4*)(embW + (size_t)t * DD);
    float4* dst = (float4*)(g_x + (size_t)r * DD);
    dst[threadIdx.x] = src[threadIdx.x];
}

__global__ void k_convWh(const float* __restrict__ lmW) {
    int v = blockIdx.x;
    int tid = threadIdx.x;
    float4 w = make_float4(0.f, 0.f, 0.f, 0.f);
    if (v < VV) w = *(const float4*)(lmW + (size_t)v*DD + tid*4);
    __half2* p = (__half2*)(g_Wh + (size_t)v*KD + tid*4);
    p[0] = __half2{__float2half_rn(w.x), __float2half_rn(w.y)};
    p[1] = __half2{__float2half_rn(w.z), __float2half_rn(w.w)};
}

// ==================== persistent step kernel ================================
// 128 CTAs x 256 threads; each CTA owns 32 rows of x resident in smem.
// R13: 4-stage B rings (deep prefetch, distance ~2.3 iters); AH/ZH share one
// region (disjoint lifetimes); WC staged in ring stage 3 so gemm2's B can be
// pre-issued before the rotate phase.
//
// smem layout (bytes):
#define O_SX    0                         // 32 x 1032 fp32 = 132096
#define O_TC    132096                    // ct 32x64 fp32  = 8192
#define O_TS    140288                    // st 32x64 fp32  = 8192
#define O_NW    148480                    // nw 1024 fp32   = 4096
#define O_RV    152576                    // rinv 32 fp32   = 128
#define O_AZ    152704                    // AH (gemm1) / ZH (gemm2), 8192
#define O_BST   160896                    // B ring 4 x 16384 = 65536
#define O_WC    210048                    // wc staging 32x132x4 = 16896 (ring stage 3)
#define STEP_SMEM 226944
#define WCP 132

__global__ void __launch_bounds__(256, 1)
k_step(const float* __restrict__ normsW,
       const float* __restrict__ stepsc,
       const float* __restrict__ onw) {
    extern __shared__ __align__(128) char smem[];
    uint32_t sb = smem_u32(smem);
    float* SX  = (float*)smem;
    float* TC  = (float*)(smem + O_TC);
    float* TS  = (float*)(smem + O_TS);
    float* NW  = (float*)(smem + O_NW);
    float* RV  = (float*)(smem + O_RV);
    float* WC  = (float*)(smem + O_WC);

    int tid = threadIdx.x, lane = tid & 31, wid = tid >> 5;
    int r0 = blockIdx.x * RPC;
    int arow = tid >> 3, au = tid & 7;     // 8 threads per owned row

    // ---- init: x rows + rotation tables into smem -------------------------
    for (int i = tid; i < RPC*256; i += 256) {       // 8192 float4
        int row = i >> 8, c4 = i & 255;
        *(float4*)(SX + (size_t)row*XP + c4*4) =
            ((const float4*)(g_x + (size_t)(r0+row)*DD))[c4];
    }
    for (int i = tid; i < RPC*FF; i += 256) {
        int row = i >> 6, f = i & 63;
        int s = (r0 + row) & (SS-1);
        TC[i] = g_ct[(size_t)s*FF + f];
        TS[i] = g_st[(size_t)s*FF + f];
    }
    __syncthreads();

    int warp_m1 = wid & 1, warp_n1 = wid >> 1;
    int lrow = ((lane >> 3) & 1) * 8 + (lane & 7);
    int uadd = lane >> 4;
    int rA1 = warp_m1*16 + lrow, sA1 = rA1 & 7;
    int rB1 = warp_n1*32 + lrow, sB1 = rB1 & 7;
    int rA2 = warp_m1*16 + lrow, sA2 = rA2 & 7;
    int rB2 = warp_n1*16 + lrow, sB2 = rB2 & 7;

    const float* xr = SX + (size_t)arow*XP;

    auto issueB1 = [&](int kt, int stg) {
        uint32_t st = sb + O_BST + stg*16384;
        #pragma unroll
        for (int j = 0; j < 4; j++) {                // 128 rows x 8 units
            int idx = tid + j*256; int row = idx >> 3, u = idx & 7;
            cp16(st + row*128 + ((u ^ (row & 7)) << 4),
                 (const char*)g_W1h + ((size_t)row*KD + kt*64 + u*8) * 2);
        }
        cp_commit();
    };
    auto issueB2 = [&](int nc, int stg) {
        uint32_t st = sb + O_BST + stg*16384;
        #pragma unroll
        for (int j = 0; j < 4; j++) {                // 2 planes x 64 rows x 8 units
            int idx = tid + j*256;
            int kc = idx >> 9, rem = idx & 511;
            int row = rem >> 3, u = rem & 7;
            cp16(st + kc*8192 + row*128 + ((u ^ (row & 7)) << 4),
                 (const char*)g_W2h + ((size_t)(nc*64+row)*K2 + kc*64 + u*8) * 2);
        }
        cp_commit();
    };

    for (int t = 0; t < TT; t++) {
        // deep prefetch: 3 B1 stages in flight before/through the rms phase
        issueB1(0, 0); issueB1(1, 1); issueB1(2, 2);

        // ---- nw + rms ------------------------------------------------------
        ((float4*)NW)[tid] = ((const float4*)(normsW + (size_t)t*DD))[tid];
        float sum = 0.f;
        #pragma unroll
        for (int kt = 0; kt < 16; kt++) {
            float4 a = *(const float4*)(xr + kt*64 + au*8);
            float4 b = *(const float4*)(xr + kt*64 + au*8 + 4);
            sum += a.x*a.x + a.y*a.y + a.z*a.z + a.w*a.w
                 + b.x*b.x + b.y*b.y + b.z*b.z + b.w*b.w;
        }
        #pragma unroll
        for (int o = 1; o < 8; o <<= 1) sum += __shfl_xor_sync(0xffffffffu, sum, o);
        if (au == 0) RV[arow] = rsqrtf(sum * (1.f/DD) + 1.1920929e-7f);
        __syncthreads();                              // RV + NW visible
        float ri = RV[arow];

        // ---- gemm1: wc = (x*ri*nw) @ W1h^T  (4-stage ring, dist ~2.3) -----
        // Invariant: all warps passed S(kt) => all completed M(kt-1).
        // issue(kt+3) overwrites stage (kt-1)&3 (reader M(kt-1) done). ✓
        float acc1[4][4] = {};
        #pragma unroll 1
        for (int kt = 0; kt < 16; kt++) {
            {   // C(kt): convert A k-tile into AZ[kt&1] (reader M(kt-2) done)
                float4 a  = *(const float4*)(xr + kt*64 + au*8);
                float4 b  = *(const float4*)(xr + kt*64 + au*8 + 4);
                float4 n0 = *(const float4*)(NW + kt*64 + au*8);
                float4 n1 = *(const float4*)(NW + kt*64 + au*8 + 4);
                __half2 h0{__float2half_rn(a.x*ri*n0.x), __float2half_rn(a.y*ri*n0.y)};
                __half2 h1{__float2half_rn(a.z*ri*n0.z), __float2half_rn(a.w*ri*n0.w)};
                __half2 h2{__float2half_rn(b.x*ri*n1.x), __float2half_rn(b.y*ri*n1.y)};
                __half2 h3{__float2half_rn(b.z*ri*n1.z), __float2half_rn(b.w*ri*n1.w)};
                uint4 pk;
                pk.x = *(uint32_t*)&h0; pk.y = *(uint32_t*)&h1;
                pk.z = *(uint32_t*)&h2; pk.w = *(uint32_t*)&h3;
                *(uint4*)(smem + O_AZ + (kt&1)*4096 + arow*128 + ((au ^ (arow&7)) << 4)) = pk;
            }
            if (kt < 14)      asm volatile("cp.async.wait_group 2;" ::: "memory");
            else if (kt < 15) asm volatile("cp.async.wait_group 1;" ::: "memory");
            else              asm volatile("cp.async.wait_group 0;" ::: "memory");
            __syncthreads();                          // S(kt)
            if (kt + 3 < 16) issueB1(kt + 3, (kt + 3) & 3);
            uint32_t stA = sb + O_AZ + (kt&1)*4096 + rA1*128;
            uint32_t stB = sb + O_BST + (kt&3)*16384 + rB1*128;
            #pragma unroll
            for (int kk = 0; kk < 4; kk++) {          // M(kt)
                uint32_t af[4], bf[2][4];
                ldm_x4(af, stA + (((kk*2 + uadd) ^ sA1) << 4));
                #pragma unroll
                for (int nt = 0; nt < 2; nt++)
                    ldm_x4(bf[nt], stB + nt*2048 + (((kk*2 + uadd) ^ sB1) << 4));
                #pragma unroll
                for (int nr = 0; nr < 4; nr++) {
                    uint32_t b2[2] = { bf[nr>>1][nr & 1], bf[nr>>1][(nr & 1) + 2] };
                    mma16816(acc1[nr], af, b2);
                }
            }
        }
        __syncthreads();                              // all M done; ring free

        // pre-issue gemm2 B stages 0-2 (land during WC write + rotate)
        issueB2(0, 0); issueB2(1, 1); issueB2(2, 2);

        // wc fragments -> WC staging (ring stage 3; gemm1 reads of st3 done)
        {
            int orow = warp_m1*16 + (lane >> 2);
            int ocol = warp_n1*32 + (lane & 3)*2;
            #pragma unroll
            for (int nr = 0; nr < 4; nr++) {
                int cc = ocol + (nr >> 1)*16 + (nr & 1)*8;
                WC[orow*WCP + cc]     = acc1[nr][0];
                WC[orow*WCP + cc + 1] = acc1[nr][1];
                WC[(orow+8)*WCP + cc]     = acc1[nr][2];
                WC[(orow+8)*WCP + cc + 1] = acc1[nr][3];
            }
        }
        __syncthreads();                              // WC visible

        // ---- rotate + fp16 convert -> ZH (AZ region; gemm1 done with it) --
        {
            int f0 = au*8;
            const float* wr = WC + arow*WCP;
            float4 a0 = *(const float4*)(wr + f0);
            float4 a1 = *(const float4*)(wr + f0 + 4);
            float4 b0 = *(const float4*)(wr + 64 + f0);
            float4 b1 = *(const float4*)(wr + 64 + f0 + 4);
            float4 c0 = *(const float4*)(TC + arow*64 + f0);
            float4 c1 = *(const float4*)(TC + arow*64 + f0 + 4);
            float4 s0 = *(const float4*)(TS + arow*64 + f0);
            float4 s1 = *(const float4*)(TS + arow*64 + f0 + 4);
            __half2 r0h{__float2half_rn(a0.x*c0.x - b0.x*s0.x), __float2half_rn(a0.y*c0.y - b0.y*s0.y)};
            __half2 r1h{__float2half_rn(a0.z*c0.z - b0.z*s0.z), __float2half_rn(a0.w*c0.w - b0.w*s0.w)};
            __half2 r2h{__float2half_rn(a1.x*c1.x - b1.x*s1.x), __float2half_rn(a1.y*c1.y - b1.y*s1.y)};
            __half2 r3h{__float2half_rn(a1.z*c1.z - b1.z*s1.z), __float2half_rn(a1.w*c1.w - b1.w*s1.w)};
            __half2 i0h{__float2half_rn(a0.x*s0.x + b0.x*c0.x), __float2half_rn(a0.y*s0.y + b0.y*c0.y)};
            __half2 i1h{__float2half_rn(a0.z*s0.z + b0.z*c0.z), __float2half_rn(a0.w*s0.w + b0.w*c0.w)};
            __half2 i2h{__float2half_rn(a1.x*s1.x + b1.x*c1.x), __float2half_rn(a1.y*s1.y + b1.y*c1.y)};
            __half2 i3h{__float2half_rn(a1.z*s1.z + b1.z*c1.z), __float2half_rn(a1.w*s1.w + b1.w*c1.w)};
            uint4 zr, zi;
            zr.x = *(uint32_t*)&r0h; zr.y = *(uint32_t*)&r1h;
            zr.z = *(uint32_t*)&r2h; zr.w = *(uint32_t*)&r3h;
            zi.x = *(uint32_t*)&i0h; zi.y = *(uint32_t*)&i1h;
            zi.z = *(uint32_t*)&i2h; zi.w = *(uint32_t*)&i3h;
            uint32_t zoff = arow*128 + ((au ^ (arow&7)) << 4);
            *(uint4*)(smem + O_AZ + zoff)        = zr;   // k-plane 0
            *(uint4*)(smem + O_AZ + 4096 + zoff) = zi;   // k-plane 1
        }
        __syncthreads();                              // ZH visible; WC free

        // ---- gemm2: x += alpha * z @ W2h^T  (4-stage ring, dist ~2.3) -----
        float alpha = 0.1f * __ldg(stepsc + t);
        #pragma unroll 1
        for (int nc = 0; nc < 16; nc++) {
            if (nc < 14)      asm volatile("cp.async.wait_group 2;" ::: "memory");
            else if (nc < 15) asm volatile("cp.async.wait_group 1;" ::: "memory");
            else              asm volatile("cp.async.wait_group 0;" ::: "memory");
            __syncthreads();                          // S(nc)
            if (nc + 3 < 16) issueB2(nc + 3, (nc + 3) & 3);   // st3 first used at nc=0: rotate done ✓
            float acc2[2][4] = {};
            #pragma unroll
            for (int kc = 0; kc < 2; kc++) {          // M(nc)
                uint32_t stA = sb + O_AZ + kc*4096 + rA2*128;
                uint32_t stB = sb + O_BST + (nc&3)*16384 + kc*8192 + rB2*128;
                #pragma unroll
                for (int kk = 0; kk < 4; kk++) {
                    uint32_t af[4], bf[4];
                    ldm_x4(af, stA + (((kk*2 + uadd) ^ sA2) << 4));
                    ldm_x4(bf, stB + (((kk*2 + uadd) ^ sB2) << 4));
                    #pragma unroll
                    for (int nr = 0; nr < 2; nr++) {
                        uint32_t b2[2] = { bf[nr], bf[nr + 2] };
                        mma16816(acc2[nr], af, b2);
                    }
                }
            }
            int orow = warp_m1*16 + (lane >> 2);      // epi(nc): writes SX only
            int ocol = nc*64 + warp_n1*16 + (lane & 3)*2;
            #pragma unroll
            for (int nr = 0; nr < 2; nr++) {
                int cc = ocol + nr*8;
                SX[orow*XP + cc]     += alpha*acc2[nr][0];
                SX[orow*XP + cc + 1] += alpha*acc2[nr][1];
                SX[(orow+8)*XP + cc]     += alpha*acc2[nr][2];
                SX[(orow+8)*XP + cc + 1] += alpha*acc2[nr][3];
            }
        }
        __syncthreads();                              // step end: SX consistent
    }

    // ---- final: rms with out_norm -> g_Xh ---------------------------------
    ((float4*)NW)[tid] = ((const float4*)onw)[tid];
    float sum = 0.f;
    #pragma unroll
    for (int kt = 0; kt < 16; kt++) {
        float4 a = *(const float4*)(xr + kt*64 + au*8);
        float4 b = *(const float4*)(xr + kt*64 + au*8 + 4);
        sum += a.x*a.x + a.y*a.y + a.z*a.z + a.w*a.w
             + b.x*b.x + b.y*b.y + b.z*b.z + b.w*b.w;
    }
    #pragma unroll
    for (int o = 1; o < 8; o <<= 1) sum += __shfl_xor_sync(0xffffffffu, sum, o);
    if (au == 0) RV[arow] = rsqrtf(sum * (1.f/DD) + 1.1920929e-7f);
    __syncthreads();
    float ri = RV[arow];
    #pragma unroll
    for (int kt = 0; kt < 16; kt++) {
        float4 a  = *(const float4*)(xr + kt*64 + au*8);
        float4 b  = *(const float4*)(xr + kt*64 + au*8 + 4);
        float4 n0 = *(const float4*)(NW + kt*64 + au*8);
        float4 n1 = *(const float4*)(NW + kt*64 + au*8 + 4);
        __half2 h0{__float2half_rn(a.x*ri*n0.x), __float2half_rn(a.y*ri*n0.y)};
        __half2 h1{__float2half_rn(a.z*ri*n0.z), __float2half_rn(a.w*ri*n0.w)};
        __half2 h2{__float2half_rn(b.x*ri*n1.x), __float2half_rn(b.y*ri*n1.y)};
        __half2 h3{__float2half_rn(b.z*ri*n1.z), __float2half_rn(b.w*ri*n1.w)};
        uint4 pk;
        pk.x = *(uint32_t*)&h0; pk.y = *(uint32_t*)&h1;
        pk.z = *(uint32_t*)&h2; pk.w = *(uint32_t*)&h3;
        *(uint4*)((char*)g_Xh + ((size_t)(r0+arow)*KD + kt*64 + au*8) * 2) = pk;
    }
}

// ==================== fp16 lm_head GEMM (4-stage) ===========================
#define STAGE_SZ 49152       // A 16K + B 32K
#define NSTG 4
#define NITK (KD/64)         // 16

__global__ void __launch_bounds__(512, 1) k_lm_mma(float* __restrict__ out) {
    extern __shared__ __align__(128) char smem[];
    uint32_t sb = smem_u32(smem);
    int tid = threadIdx.x;
    int lane = tid & 31, wid = tid >> 5;
    int warp_m = wid & 3, warp_n = wid >> 2;
    int r0 = blockIdx.x * 128;      // M fastest: A stays L2-resident, B streams once
    int n0 = blockIdx.y * 256;

    const char* srcA = (const char*)g_Xh + ((size_t)r0 * KD) * 2;
    const char* srcB = (const char*)g_Wh + ((size_t)n0 * KD) * 2;

    int lrow = ((lane >> 3) & 1) * 8 + (lane & 7);
    int uadd = lane >> 4;
    int rA = warp_m * 32 + lrow;
    int rB = warp_n * 64 + lrow;
    int sA = rA & 7, sB = rB & 7;
    uint32_t aBase = sb + rA * 128;
    uint32_t bBase = sb + 16384 + rB * 128;

    float acc[2][8][4] = {};

    auto issue = [&](int kt, int stg) {
        uint32_t st = sb + stg * STAGE_SZ;
        #pragma unroll
        for (int j = 0; j < 2; j++) {
            int idx = tid + j*512;
            int row = idx >> 3, u = idx & 7;
            cp16(st + row*128 + ((u ^ (row & 7)) << 4),
                 srcA + ((size_t)row*KD + kt*64 + u*8) * 2);
        }
        #pragma unroll
        for (int j = 0; j < 4; j++) {
            int idx = tid + j*512;
            int row = idx >> 3, u = idx & 7;
            cp16(st + 16384 + row*128 + ((u ^ (row & 7)) << 4),
                 srcB + ((size_t)row*KD + kt*64 + u*8) * 2);
        }
        cp_commit();
    };

    issue(0, 0); issue(1, 1); issue(2, 2);

    for (int kt = 0; kt < NITK; kt++) {
        if (kt < NITK-2)      asm volatile("cp.async.wait_group 2;" ::: "memory");
        else if (kt < NITK-1) asm volatile("cp.async.wait_group 1;" ::: "memory");
        else                  asm volatile("cp.async.wait_group 0;" ::: "memory");
        __syncthreads();
        if (kt + 3 < NITK) issue(kt + 3, (kt + 3) & 3);

        uint32_t stA = aBase + (kt & 3) * STAGE_SZ;
        uint32_t stB = bBase + (kt & 3) * STAGE_SZ;
        #pragma unroll
        for (int kk = 0; kk < 4; kk++) {
            uint32_t af[2][4], bf[4][4];
            #pragma unroll
            for (int mt = 0; mt < 2; mt++)
                ldm_x4(af[mt], stA + mt*2048 + (((kk*2 + uadd) ^ sA) << 4));
            #pragma unroll
            for (int nt = 0; nt < 4; nt++)
                ldm_x4(bf[nt], stB + nt*2048 + (((kk*2 + uadd) ^ sB) << 4));
            #pragma unroll
            for (int mt = 0; mt < 2; mt++)
                #pragma unroll
                for (int nr = 0; nr < 8; nr++) {
                    uint32_t b2[2] = { bf[nr>>1][nr & 1], bf[nr>>1][(nr & 1) + 2] };
                    mma16816(acc[mt][nr], af[mt], b2);
                }
        }
        __syncthreads();
    }

    int orow = r0 + warp_m*32 + (lane >> 2);
    int ocol = n0 + warp_n*64 + (lane & 3)*2;
    #pragma unroll
    for (int mt = 0; mt < 2; mt++) {
        #pragma unroll
        for (int nr = 0; nr < 8; nr++) {
            int cc = ocol + (nr >> 1)*16 + (nr & 1)*8;
            size_t p0 = (size_t)(orow + mt*16)     * VV + cc;
            size_t p1 = (size_t)(orow + mt*16 + 8) * VV + cc;
            if (cc < VV)     { out[p0]   = acc[mt][nr][0]; out[p1]   = acc[mt][nr][2]; }
            if (cc + 1 < VV) { out[p0+1] = acc[mt][nr][1]; out[p1+1] = acc[mt][nr][3]; }
        }
    }
}

// ==================== launch ================================================
extern "C" void kernel_launch(void* const* d_in, const int* in_sizes, int n_in,
                              void* d_out, int out_size) {
    const int*   tokens   = (const int*)  d_in[0];
    const float* embW     = (const float*)d_in[1];
    const float* toW      = (const float*)d_in[2];
    const float* fwW      = (const float*)d_in[3];
    const float* speed    = (const float*)d_in[4];
    const float* dampen   = (const float*)d_in[5];
    const float* phase    = (const float*)d_in[6];
    const float* coupling = (const float*)d_in[7];
    const float* stepsc   = (const float*)d_in[8];
    const float* posf     = (const float*)d_in[9];
    const float* normsW   = (const float*)d_in[10];
    const float* onw      = (const float*)d_in[11];
    const float* lmW      = (const float*)d_in[12];
    float* out = (float*)d_out;

    cudaFuncSetAttribute(k_lm_mma, cudaFuncAttributeMaxDynamicSharedMemorySize, NSTG*STAGE_SZ);
    cudaFuncSetAttribute(k_step,   cudaFuncAttributeMaxDynamicSharedMemorySize, STEP_SMEM);

    k_prep_w2h<<<(DD*K2 + 255)/256, 256>>>(speed, dampen, phase, coupling, fwW);
    k_convW1h<<<2*FF, 256>>>(toW);
    k_tables<<<(SS*FF + 255)/256, 256>>>(posf);
    k_embed<<<MM, 256>>>(tokens, embW);
    k_convWh<<<NPAD, 256>>>(lmW);

    k_step<<<MM/RPC, 256, STEP_SMEM>>>(normsW, stepsc, onw);

    k_lm_mma<<<dim3(MM/128, NPAD/256), 512, NSTG*STAGE_SZ>>>(out);
}